// round 4
// baseline (speedup 1.0000x reference)
#include <cuda_runtime.h>
#include <cuda_bf16.h>
#include <math.h>
#include <stdint.h>

#define NN 50000
#define EE 300000
#define DD 256
#define FF 1024
#define CC 40

// ======================= helpers =======================
__device__ __forceinline__ uint32_t smem_u32(const void* p) {
    uint32_t a;
    asm("{ .reg .u64 t; cvta.to.shared.u64 t, %1; cvt.u32.u64 %0, t; }" : "=r"(a) : "l"(p));
    return a;
}
__device__ __forceinline__ void mma_bf16(float* c, const uint32_t* a, const uint32_t* b) {
    asm volatile(
        "mma.sync.aligned.m16n8k16.row.col.f32.bf16.bf16.f32 "
        "{%0,%1,%2,%3}, {%4,%5,%6,%7}, {%8,%9}, {%0,%1,%2,%3};"
        : "+f"(c[0]), "+f"(c[1]), "+f"(c[2]), "+f"(c[3])
        : "r"(a[0]), "r"(a[1]), "r"(a[2]), "r"(a[3]), "r"(b[0]), "r"(b[1]));
}
__device__ __forceinline__ void ldsm4(uint32_t* r, uint32_t addr) {
    asm volatile("ldmatrix.sync.aligned.m8n8.x4.shared.b16 {%0,%1,%2,%3}, [%4];"
                 : "=r"(r[0]), "=r"(r[1]), "=r"(r[2]), "=r"(r[3]) : "r"(addr));
}
__device__ __forceinline__ void ldsm4t(uint32_t* r, uint32_t addr) {
    asm volatile("ldmatrix.sync.aligned.m8n8.x4.trans.shared.b16 {%0,%1,%2,%3}, [%4];"
                 : "=r"(r[0]), "=r"(r[1]), "=r"(r[2]), "=r"(r[3]) : "r"(addr));
}
__device__ __forceinline__ uint32_t packbf(float x, float y) {
    __nv_bfloat162 t = __floats2bfloat162_rn(x, y);
    return *reinterpret_cast<uint32_t*>(&t);
}
__device__ __forceinline__ void split4(float4 v, uint32_t* hi, uint32_t* lo) {
    float hx = __bfloat162float(__float2bfloat16(v.x));
    float hy = __bfloat162float(__float2bfloat16(v.y));
    float hz = __bfloat162float(__float2bfloat16(v.z));
    float hw = __bfloat162float(__float2bfloat16(v.w));
    hi[0] = packbf(v.x, v.y);
    hi[1] = packbf(v.z, v.w);
    lo[0] = packbf(v.x - hx, v.y - hy);
    lo[1] = packbf(v.z - hz, v.w - hw);
}
__device__ __forceinline__ void cp16(uint32_t dst, const void* src, uint32_t srcsize) {
    asm volatile("cp.async.cg.shared.global [%0], [%1], 16, %2;"
                 :: "r"(dst), "l"(src), "r"(srcsize) : "memory");
}
__device__ __forceinline__ void cp16f(uint32_t dst, const void* src) {
    asm volatile("cp.async.cg.shared.global [%0], [%1], 16;"
                 :: "r"(dst), "l"(src) : "memory");
}
__device__ __forceinline__ void cp_commit() {
    asm volatile("cp.async.commit_group;" ::: "memory");
}
template <int Ng>
__device__ __forceinline__ void cp_wait() {
    asm volatile("cp.async.wait_group %0;" :: "n"(Ng) : "memory");
}

// ======================= device scratch =======================
__device__ float g_x[NN * DD];
__device__ float g_norm_s[NN];
__device__ float g_norm_d[NN];
__device__ int   g_deg_out[NN];
__device__ int   g_deg_in[NN];
__device__ int   g_rowptr[NN + 1];
__device__ int   g_cursor[NN];
__device__ int   g_col[EE];
__device__ int   g_blocksums[128];
__device__ float g_colsum[DD];
__device__ float g_colsq[DD];
// split operand buffers
__device__ __nv_bfloat16 g_feat_hi[NN * FF];
__device__ __nv_bfloat16 g_feat_lo[NN * FF];
__device__ __nv_bfloat16 g_m_hi[NN * DD];
__device__ __nv_bfloat16 g_m_lo[NN * DD];
__device__ __nv_bfloat16 g_w_hi[FF * DD];
__device__ __nv_bfloat16 g_w_lo[FF * DD];

// ======================= utility kernels =======================
__global__ void zero_init_kernel() {
    int i = blockIdx.x * blockDim.x + threadIdx.x;
    if (i < NN) { g_deg_out[i] = 0; g_deg_in[i] = 0; g_cursor[i] = 0; }
}
__global__ void zero_bn_kernel() {
    int t = threadIdx.x;
    if (t < DD) { g_colsum[t] = 0.f; g_colsq[t] = 0.f; }
}
__global__ void count_deg_kernel(const int* __restrict__ src, const int* __restrict__ dst) {
    int e = blockIdx.x * blockDim.x + threadIdx.x;
    if (e < EE) {
        atomicAdd(&g_deg_out[src[e]], 1);
        atomicAdd(&g_deg_in[dst[e]], 1);
    }
}
__global__ void norms_kernel() {
    int i = blockIdx.x * blockDim.x + threadIdx.x;
    if (i < NN) {
        g_norm_s[i] = rsqrtf(fmaxf((float)g_deg_out[i], 1.f));
        g_norm_d[i] = rsqrtf(fmaxf((float)g_deg_in[i], 1.f));
    }
}

#define SCAN_CHUNK 512
__global__ void scan_part_kernel() {
    __shared__ int sh[SCAN_CHUNK];
    int t = threadIdx.x;
    int i = blockIdx.x * SCAN_CHUNK + t;
    int v = (i < NN) ? g_deg_in[i] : 0;
    sh[t] = v;
    __syncthreads();
    for (int off = 1; off < SCAN_CHUNK; off <<= 1) {
        int add = (t >= off) ? sh[t - off] : 0;
        __syncthreads();
        sh[t] += add;
        __syncthreads();
    }
    if (i < NN) g_rowptr[i + 1] = sh[t];
    if (t == SCAN_CHUNK - 1) g_blocksums[blockIdx.x] = sh[t];
}
__global__ void scan_block_kernel(int nblocks) {
    __shared__ int sh[128];
    int t = threadIdx.x;
    int v = (t < nblocks) ? g_blocksums[t] : 0;
    sh[t] = v;
    __syncthreads();
    for (int off = 1; off < 128; off <<= 1) {
        int add = (t >= off) ? sh[t - off] : 0;
        __syncthreads();
        sh[t] += add;
        __syncthreads();
    }
    if (t < nblocks) g_blocksums[t] = sh[t];
}
__global__ void scan_add_kernel() {
    int t = threadIdx.x;
    int b = blockIdx.x;
    int i = b * SCAN_CHUNK + t;
    int off = (b > 0) ? g_blocksums[b - 1] : 0;
    if (i < NN) g_rowptr[i + 1] += off;
    if (b == 0 && t == 0) g_rowptr[0] = 0;
}
__global__ void fill_csr_kernel(const int* __restrict__ src, const int* __restrict__ dst) {
    int e = blockIdx.x * blockDim.x + threadIdx.x;
    if (e < EE) {
        int d = dst[e];
        int p = g_rowptr[d] + atomicAdd(&g_cursor[d], 1);
        g_col[p] = src[e];
    }
}

// ---------------- elementwise split fp32 -> bf16 hi/lo ----------------
__global__ void split_kernel(const float* __restrict__ X,
                             __nv_bfloat16* __restrict__ Hi,
                             __nv_bfloat16* __restrict__ Lo, int n4) {
    int i = blockIdx.x * blockDim.x + threadIdx.x;
    if (i >= n4) return;
    float4 v = __ldg((const float4*)X + i);
    uint32_t hi[2], lo[2];
    split4(v, hi, lo);
    ((uint2*)Hi)[i] = make_uint2(hi[0], hi[1]);
    ((uint2*)Lo)[i] = make_uint2(lo[0], lo[1]);
}

// ---------------- SpMM (emits split bf16 output) ----------------
__global__ void __launch_bounds__(256) spmm_split_kernel(const float* __restrict__ X,
                                                         __nv_bfloat16* __restrict__ Mhi,
                                                         __nv_bfloat16* __restrict__ Mlo) {
    int wg = (blockIdx.x * blockDim.x + threadIdx.x) >> 5;
    if (wg >= NN) return;
    int lane = threadIdx.x & 31;
    int s0 = g_rowptr[wg], s1 = g_rowptr[wg + 1];
    float4 a0 = {0, 0, 0, 0}, a1 = {0, 0, 0, 0};
    for (int e = s0; e < s1; e++) {
        int s = g_col[e];
        float ns = g_norm_s[s];
        const float4* xp = (const float4*)(X + (size_t)s * DD);
        float4 v0 = __ldg(xp + lane);
        float4 v1 = __ldg(xp + lane + 32);
        a0.x += v0.x * ns; a0.y += v0.y * ns; a0.z += v0.z * ns; a0.w += v0.w * ns;
        a1.x += v1.x * ns; a1.y += v1.y * ns; a1.z += v1.z * ns; a1.w += v1.w * ns;
    }
    float nd = g_norm_d[wg];
    a0.x *= nd; a0.y *= nd; a0.z *= nd; a0.w *= nd;
    a1.x *= nd; a1.y *= nd; a1.z *= nd; a1.w *= nd;
    uint32_t hi[2], lo[2];
    size_t base = (size_t)wg * DD;
    split4(a0, hi, lo);
    ((uint2*)(Mhi + base))[lane] = make_uint2(hi[0], hi[1]);
    ((uint2*)(Mlo + base))[lane] = make_uint2(lo[0], lo[1]);
    split4(a1, hi, lo);
    ((uint2*)(Mhi + base))[lane + 32] = make_uint2(hi[0], hi[1]);
    ((uint2*)(Mlo + base))[lane + 32] = make_uint2(lo[0], lo[1]);
}

// ---------------- BatchNorm ----------------
__global__ void bn_stats_kernel(const float* __restrict__ X) {
    int t = threadIdx.x;
    float s = 0.f, q = 0.f;
    for (int r = blockIdx.x; r < NN; r += gridDim.x) {
        float v = X[(size_t)r * DD + t];
        s += v;
        q += v * v;
    }
    atomicAdd(&g_colsum[t], s);
    atomicAdd(&g_colsq[t], q);
}
__global__ void bn_elu_kernel(float* __restrict__ X,
                              const float* __restrict__ gamma,
                              const float* __restrict__ beta) {
    int idx = blockIdx.x * blockDim.x + threadIdx.x;
    int col = idx & (DD - 1);
    float mu = g_colsum[col] * (1.f / NN);
    float var = g_colsq[col] * (1.f / NN) - mu * mu;
    float inv = rsqrtf(var + 1e-5f);
    float y = gamma[col] * (X[idx] - mu) * inv + beta[col];
    X[idx] = (y > 0.f) ? y : expm1f(y);
}

// ======================= double-buffered bf16x3 GEMM, 128x256 tile =======================
#define SA_STR 80      // 32 bf16 (64B) + 16B pad
#define SB_STR 528     // 256 bf16 (512B) + 16B pad
#define A_BUF (128 * SA_STR)
#define B_BUF (32 * SB_STR)
#define BUF_SZ (2 * A_BUF + 2 * B_BUF)
#define GEMM_SMEM (2 * BUF_SZ)

__global__ void __launch_bounds__(512) gemm_split_kernel(
    const __nv_bfloat16* __restrict__ Ahi, const __nv_bfloat16* __restrict__ Alo,
    const __nv_bfloat16* __restrict__ Bhi, const __nv_bfloat16* __restrict__ Blo,
    const float* __restrict__ bias, float* __restrict__ C,
    int M, int K)   // N fixed = 256
{
    extern __shared__ __align__(16) uint8_t smem[];
    const uint32_t sbase = smem_u32(smem);

    const int tid = threadIdx.x;
    const int wid = tid >> 5;
    const int lane = tid & 31;
    const int warpM = (wid & 3) * 32;
    const int warpN = (wid >> 2) * 64;
    const int bm = blockIdx.x * 128;

    // cp.async roles
    const int a_row = tid >> 2;                       // 0..127
    const uint32_t a_dst = (uint32_t)(a_row * SA_STR + (tid & 3) * 16);
    const uint8_t* a_src_hi = (const uint8_t*)(Ahi + (size_t)(bm + a_row) * K) + (tid & 3) * 16;
    const uint8_t* a_src_lo = (const uint8_t*)(Alo + (size_t)(bm + a_row) * K) + (tid & 3) * 16;
    const uint32_t a_ok = (bm + a_row < M) ? 16u : 0u;
    const int b_row0 = tid >> 5;                      // 0..15
    const int b_cb0  = (tid & 31) * 16;               // 0..496
    // second B chunk: rows 16..31
    const int b_row1 = b_row0 + 16;

    // ldmatrix per-lane offsets
    const int m8 = lane >> 3;
    const int r8 = lane & 7;
    const uint32_t aoff = (uint32_t)(((m8 & 1) * 8 + r8) * SA_STR + (m8 >> 1) * 16);
    const uint32_t boff = (uint32_t)(((m8 & 1) * 8 + r8) * SB_STR + (m8 >> 1) * 16);

    float acc[2][8][4];
#pragma unroll
    for (int i = 0; i < 2; i++)
#pragma unroll
        for (int j = 0; j < 8; j++)
#pragma unroll
            for (int q = 0; q < 4; q++) acc[i][j][q] = 0.f;

    const int KT = K >> 5;

    // ---- loader ----
    auto load_chunk = [&](int k0, int buf) {
        uint32_t d = sbase + buf * BUF_SZ;
        cp16(d + a_dst, a_src_hi + (size_t)k0 * 2, a_ok);
        cp16(d + A_BUF + a_dst, a_src_lo + (size_t)k0 * 2, a_ok);
        uint32_t db = d + 2 * A_BUF;
        const uint8_t* sh0 = (const uint8_t*)Bhi + (size_t)(k0 + b_row0) * 512 + b_cb0;
        const uint8_t* sl0 = (const uint8_t*)Blo + (size_t)(k0 + b_row0) * 512 + b_cb0;
        const uint8_t* sh1 = (const uint8_t*)Bhi + (size_t)(k0 + b_row1) * 512 + b_cb0;
        const uint8_t* sl1 = (const uint8_t*)Blo + (size_t)(k0 + b_row1) * 512 + b_cb0;
        cp16f(db + b_row0 * SB_STR + b_cb0, sh0);
        cp16f(db + b_row1 * SB_STR + b_cb0, sh1);
        cp16f(db + B_BUF + b_row0 * SB_STR + b_cb0, sl0);
        cp16f(db + B_BUF + b_row1 * SB_STR + b_cb0, sl1);
        cp_commit();
    };

    load_chunk(0, 0);

    for (int it = 0; it < KT; ++it) {
        const int buf = it & 1;
        if (it + 1 < KT) {
            load_chunk((it + 1) << 5, buf ^ 1);
            cp_wait<1>();
        } else {
            cp_wait<0>();
        }
        __syncthreads();

        const uint32_t base = sbase + buf * BUF_SZ;
#pragma unroll
        for (int kh = 0; kh < 2; kh++) {
            uint32_t ah[2][4], al[2][4], b[16];
            const uint32_t aW = base + (uint32_t)(warpM * SA_STR + kh * 32) + aoff;
            const uint32_t bW = base + 2 * A_BUF + (uint32_t)(kh * 16 * SB_STR + warpN * 2) + boff;
#pragma unroll
            for (int mt = 0; mt < 2; mt++) {
                ldsm4(ah[mt], aW + mt * 16 * SA_STR);
                ldsm4(al[mt], aW + A_BUF + mt * 16 * SA_STR);
            }
#pragma unroll
            for (int p = 0; p < 4; p++) ldsm4t(&b[4 * p], bW + p * 32);
            // pass 1: Ah*Bh, pass 2: Al*Bh
#pragma unroll
            for (int mt = 0; mt < 2; mt++)
#pragma unroll
                for (int nt = 0; nt < 8; nt++)
                    mma_bf16(acc[mt][nt], ah[mt], &b[nt * 2]);
#pragma unroll
            for (int mt = 0; mt < 2; mt++)
#pragma unroll
                for (int nt = 0; nt < 8; nt++)
                    mma_bf16(acc[mt][nt], al[mt], &b[nt * 2]);
            // reload B as lo, pass 3: Ah*Bl
#pragma unroll
            for (int p = 0; p < 4; p++) ldsm4t(&b[4 * p], bW + B_BUF + p * 32);
#pragma unroll
            for (int mt = 0; mt < 2; mt++)
#pragma unroll
                for (int nt = 0; nt < 8; nt++)
                    mma_bf16(acc[mt][nt], ah[mt], &b[nt * 2]);
        }
        __syncthreads();
    }

    // ---- epilogue (N = 256 exact) ----
    const int g = lane >> 2;
    const int tg = lane & 3;
#pragma unroll
    for (int mt = 0; mt < 2; mt++) {
        int row0 = bm + warpM + mt * 16 + g;
        int row1 = row0 + 8;
#pragma unroll
        for (int nt = 0; nt < 8; nt++) {
            int col0 = warpN + nt * 8 + tg * 2;
            float bi0 = __ldg(bias + col0);
            float bi1 = __ldg(bias + col0 + 1);
            if (row0 < M) {
                C[(size_t)row0 * 256 + col0]     = acc[mt][nt][0] + bi0;
                C[(size_t)row0 * 256 + col0 + 1] = acc[mt][nt][1] + bi1;
            }
            if (row1 < M) {
                C[(size_t)row1 * 256 + col0]     = acc[mt][nt][2] + bi0;
                C[(size_t)row1 * 256 + col0 + 1] = acc[mt][nt][3] + bi1;
            }
        }
    }
}

// ======================= logits GEMM (small, in-kernel split, 128x128 tile) =======================
#define SA_STRIDE 80
#define SB_STRIDE 272
__global__ void __launch_bounds__(256) gemm_mma_kernel(
    const float* __restrict__ A, const float* __restrict__ B,
    const float* __restrict__ bias, float* __restrict__ C,
    int M, int N, int K)
{
    __shared__ __align__(16) uint8_t sAhi[128 * SA_STRIDE];
    __shared__ __align__(16) uint8_t sAlo[128 * SA_STRIDE];
    __shared__ __align__(16) uint8_t sBhi[32 * SB_STRIDE];
    __shared__ __align__(16) uint8_t sBlo[32 * SB_STRIDE];

    const int tid = threadIdx.x;
    const int wid = tid >> 5;
    const int lane = tid & 31;
    const int warpM = (wid & 3) * 32;
    const int warpN = (wid >> 2) * 64;
    const int bm = blockIdx.x * 128;
    const int bn = blockIdx.y * 128;

    const uint32_t uAhi = smem_u32(sAhi);
    const uint32_t uAlo = smem_u32(sAlo);
    const uint32_t uBhi = smem_u32(sBhi);
    const uint32_t uBlo = smem_u32(sBlo);

    const int m8 = lane >> 3;
    const int r8 = lane & 7;
    const uint32_t aoff = (uint32_t)(((m8 & 1) * 8 + r8) * SA_STRIDE + (m8 >> 1) * 16);
    const uint32_t boff = (uint32_t)(((m8 & 1) * 8 + r8) * SB_STRIDE + (m8 >> 1) * 16);

    float acc[2][8][4];
#pragma unroll
    for (int i = 0; i < 2; i++)
#pragma unroll
        for (int j = 0; j < 8; j++)
#pragma unroll
            for (int q = 0; q < 4; q++) acc[i][j][q] = 0.f;

    const int arow = tid >> 1;
    const int acb  = (tid & 1) * 16;
    const int bkr  = tid >> 3;
    const int bcb  = (tid & 7) * 16;

    for (int k0 = 0; k0 < K; k0 += 32) {
        {
            float4 f[4];
            if (bm + arow < M) {
                const float4* p = (const float4*)(A + (size_t)(bm + arow) * K + k0 + acb);
#pragma unroll
                for (int q = 0; q < 4; q++) f[q] = __ldg(p + q);
            } else {
#pragma unroll
                for (int q = 0; q < 4; q++) f[q] = make_float4(0.f, 0.f, 0.f, 0.f);
            }
            uint32_t hi[8], lo[8];
#pragma unroll
            for (int q = 0; q < 4; q++) split4(f[q], hi + 2 * q, lo + 2 * q);
            uint8_t* dh = sAhi + arow * SA_STRIDE + acb * 2;
            uint8_t* dl = sAlo + arow * SA_STRIDE + acb * 2;
            *(uint4*)dh        = make_uint4(hi[0], hi[1], hi[2], hi[3]);
            *(uint4*)(dh + 16) = make_uint4(hi[4], hi[5], hi[6], hi[7]);
            *(uint4*)dl        = make_uint4(lo[0], lo[1], lo[2], lo[3]);
            *(uint4*)(dl + 16) = make_uint4(lo[4], lo[5], lo[6], lo[7]);
        }
        {
            float4 f[4];
            const size_t brow = (size_t)(k0 + bkr) * N;
            if (bn + bcb + 15 < N) {
                const float4* p = (const float4*)(B + brow + bn + bcb);
#pragma unroll
                for (int q = 0; q < 4; q++) f[q] = __ldg(p + q);
            } else {
                float v[16];
#pragma unroll
                for (int i = 0; i < 16; i++) {
                    int c = bn + bcb + i;
                    v[i] = (c < N) ? __ldg(B + brow + c) : 0.f;
                }
#pragma unroll
                for (int q = 0; q < 4; q++) f[q] = make_float4(v[4*q], v[4*q+1], v[4*q+2], v[4*q+3]);
            }
            uint32_t hi[8], lo[8];
#pragma unroll
            for (int q = 0; q < 4; q++) split4(f[q], hi + 2 * q, lo + 2 * q);
            uint8_t* dh = sBhi + bkr * SB_STRIDE + bcb * 2;
            uint8_t* dl = sBlo + bkr * SB_STRIDE + bcb * 2;
            *(uint4*)dh        = make_uint4(hi[0], hi[1], hi[2], hi[3]);
            *(uint4*)(dh + 16) = make_uint4(hi[4], hi[5], hi[6], hi[7]);
            *(uint4*)dl        = make_uint4(lo[0], lo[1], lo[2], lo[3]);
            *(uint4*)(dl + 16) = make_uint4(lo[4], lo[5], lo[6], lo[7]);
        }
        __syncthreads();

#pragma unroll
        for (int kh = 0; kh < 2; kh++) {
            uint32_t afrag[2][4];
            uint32_t bh[16], bl[16];
            const uint32_t aW = (uint32_t)(warpM * SA_STRIDE + kh * 32) + aoff;
            const uint32_t bW = (uint32_t)(kh * 16 * SB_STRIDE + warpN * 2) + boff;
#pragma unroll
            for (int mt = 0; mt < 2; mt++)
                ldsm4(afrag[mt], uAhi + aW + mt * 16 * SA_STRIDE);
#pragma unroll
            for (int p = 0; p < 4; p++)
                ldsm4t(&bh[4 * p], uBhi + bW + p * 32);
#pragma unroll
            for (int mt = 0; mt < 2; mt++)
#pragma unroll
                for (int nt = 0; nt < 8; nt++)
                    mma_bf16(acc[mt][nt], afrag[mt], &bh[nt * 2]);
#pragma unroll
            for (int p = 0; p < 4; p++)
                ldsm4t(&bl[4 * p], uBlo + bW + p * 32);
#pragma unroll
            for (int mt = 0; mt < 2; mt++)
#pragma unroll
                for (int nt = 0; nt < 8; nt++)
                    mma_bf16(acc[mt][nt], afrag[mt], &bl[nt * 2]);
#pragma unroll
            for (int mt = 0; mt < 2; mt++)
                ldsm4(afrag[mt], uAlo + aW + mt * 16 * SA_STRIDE);
#pragma unroll
            for (int mt = 0; mt < 2; mt++)
#pragma unroll
                for (int nt = 0; nt < 8; nt++)
                    mma_bf16(acc[mt][nt], afrag[mt], &bh[nt * 2]);
        }
        __syncthreads();
    }

    const int g  = lane >> 2;
    const int tg = lane & 3;
#pragma unroll
    for (int mt = 0; mt < 2; mt++) {
        int row0 = bm + warpM + mt * 16 + g;
        int row1 = row0 + 8;
#pragma unroll
        for (int nt = 0; nt < 8; nt++) {
            int col0 = bn + warpN + nt * 8 + tg * 2;
            if (col0 < N) {
                float bi0 = __ldg(bias + col0);
                bool c1ok = (col0 + 1 < N);
                float bi1 = c1ok ? __ldg(bias + col0 + 1) : 0.f;
                if (row0 < M) {
                    C[(size_t)row0 * N + col0] = acc[mt][nt][0] + bi0;
                    if (c1ok) C[(size_t)row0 * N + col0 + 1] = acc[mt][nt][1] + bi1;
                }
                if (row1 < M) {
                    C[(size_t)row1 * N + col0] = acc[mt][nt][2] + bi0;
                    if (c1ok) C[(size_t)row1 * N + col0 + 1] = acc[mt][nt][3] + bi1;
                }
            }
        }
    }
}

// ======================= launch =======================
extern "C" void kernel_launch(void* const* d_in, const int* in_sizes, int n_in,
                              void* d_out, int out_size) {
    const float* feat  = (const float*)d_in[0];
    const int*   src   = (const int*)d_in[1];
    const int*   dst   = (const int*)d_in[2];
    const float* W_fc  = (const float*)d_in[3];
    const float* b_fc  = (const float*)d_in[4];
    const float* W1    = (const float*)d_in[5];
    const float* b1    = (const float*)d_in[6];
    const float* W2    = (const float*)d_in[7];
    const float* b2    = (const float*)d_in[8];
    const float* W3    = (const float*)d_in[9];
    const float* b3    = (const float*)d_in[10];
    const float* gamma = (const float*)d_in[11];
    const float* beta  = (const float*)d_in[12];
    const float* W_lin = (const float*)d_in[13];
    const float* b_lin = (const float*)d_in[14];

    float* out_x      = (float*)d_out;
    float* out_logits = (float*)d_out + (size_t)NN * DD;

    float* gx;  cudaGetSymbolAddress((void**)&gx, g_x);
    __nv_bfloat16 *fh, *fl, *mh, *ml, *wh, *wl;
    cudaGetSymbolAddress((void**)&fh, g_feat_hi);
    cudaGetSymbolAddress((void**)&fl, g_feat_lo);
    cudaGetSymbolAddress((void**)&mh, g_m_hi);
    cudaGetSymbolAddress((void**)&ml, g_m_lo);
    cudaGetSymbolAddress((void**)&wh, g_w_hi);
    cudaGetSymbolAddress((void**)&wl, g_w_lo);

    cudaFuncSetAttribute(gemm_split_kernel, cudaFuncAttributeMaxDynamicSharedMemorySize, GEMM_SMEM);

    int nscan = (NN + SCAN_CHUNK - 1) / SCAN_CHUNK;

    zero_init_kernel<<<(NN + 255) / 256, 256>>>();
    count_deg_kernel<<<(EE + 255) / 256, 256>>>(src, dst);
    norms_kernel<<<(NN + 255) / 256, 256>>>();
    scan_part_kernel<<<nscan, SCAN_CHUNK>>>();
    scan_block_kernel<<<1, 128>>>(nscan);
    scan_add_kernel<<<nscan, SCAN_CHUNK>>>();
    fill_csr_kernel<<<(EE + 255) / 256, 256>>>(src, dst);

    const int MT = (NN + 127) / 128;   // 391
    int spmm_blocks = (NN * 32 + 255) / 256;
    int elem_blocks = (NN * DD) / 256;

    // pre-split feat and W_fc
    split_kernel<<<(NN * FF / 4 + 255) / 256, 256>>>(feat, fh, fl, NN * FF / 4);
    split_kernel<<<(FF * DD / 4 + 255) / 256, 256>>>(W_fc, wh, wl, FF * DD / 4);
    // x = feat @ W_fc + b_fc
    gemm_split_kernel<<<MT, 512, GEMM_SMEM>>>(fh, fl, wh, wl, b_fc, gx, NN, FF);

    // layer 1
    spmm_split_kernel<<<spmm_blocks, 256>>>(gx, mh, ml);
    split_kernel<<<(DD * DD / 4 + 255) / 256, 256>>>(W1, wh, wl, DD * DD / 4);
    gemm_split_kernel<<<MT, 512, GEMM_SMEM>>>(mh, ml, wh, wl, b1, gx, NN, DD);
    zero_bn_kernel<<<1, 256>>>();
    bn_stats_kernel<<<256, 256>>>(gx);
    bn_elu_kernel<<<elem_blocks, 256>>>(gx, gamma, beta);

    // layer 2
    spmm_split_kernel<<<spmm_blocks, 256>>>(gx, mh, ml);
    split_kernel<<<(DD * DD / 4 + 255) / 256, 256>>>(W2, wh, wl, DD * DD / 4);
    gemm_split_kernel<<<MT, 512, GEMM_SMEM>>>(mh, ml, wh, wl, b2, gx, NN, DD);
    zero_bn_kernel<<<1, 256>>>();
    bn_stats_kernel<<<256, 256>>>(gx);
    bn_elu_kernel<<<elem_blocks, 256>>>(gx, gamma, beta);

    // layer 3 (no BN) -> out_x
    spmm_split_kernel<<<spmm_blocks, 256>>>(gx, mh, ml);
    split_kernel<<<(DD * DD / 4 + 255) / 256, 256>>>(W3, wh, wl, DD * DD / 4);
    gemm_split_kernel<<<MT, 512, GEMM_SMEM>>>(mh, ml, wh, wl, b3, out_x, NN, DD);

    // logits = out_x @ W_lin + b_lin
    dim3 g_lin(MT, 1);
    gemm_mma_kernel<<<g_lin, 256>>>(out_x, W_lin, b_lin, out_logits, NN, CC, DD);
}

// round 5
// speedup vs baseline: 1.4849x; 1.4849x over previous
#include <cuda_runtime.h>
#include <cuda_bf16.h>
#include <math.h>
#include <stdint.h>

#define NN 50000
#define EE 300000
#define DD 256
#define FF 1024
#define CC 40

// ======================= helpers =======================
__device__ __forceinline__ uint32_t smem_u32(const void* p) {
    uint32_t a;
    asm("{ .reg .u64 t; cvta.to.shared.u64 t, %1; cvt.u32.u64 %0, t; }" : "=r"(a) : "l"(p));
    return a;
}
__device__ __forceinline__ void mma_bf16(float* c, const uint32_t* a, const uint32_t* b) {
    asm volatile(
        "mma.sync.aligned.m16n8k16.row.col.f32.bf16.bf16.f32 "
        "{%0,%1,%2,%3}, {%4,%5,%6,%7}, {%8,%9}, {%0,%1,%2,%3};"
        : "+f"(c[0]), "+f"(c[1]), "+f"(c[2]), "+f"(c[3])
        : "r"(a[0]), "r"(a[1]), "r"(a[2]), "r"(a[3]), "r"(b[0]), "r"(b[1]));
}
__device__ __forceinline__ void ldsm4(uint32_t* r, uint32_t addr) {
    asm volatile("ldmatrix.sync.aligned.m8n8.x4.shared.b16 {%0,%1,%2,%3}, [%4];"
                 : "=r"(r[0]), "=r"(r[1]), "=r"(r[2]), "=r"(r[3]) : "r"(addr));
}
__device__ __forceinline__ void ldsm4t(uint32_t* r, uint32_t addr) {
    asm volatile("ldmatrix.sync.aligned.m8n8.x4.trans.shared.b16 {%0,%1,%2,%3}, [%4];"
                 : "=r"(r[0]), "=r"(r[1]), "=r"(r[2]), "=r"(r[3]) : "r"(addr));
}
__device__ __forceinline__ uint32_t packbf(float x, float y) {
    __nv_bfloat162 t = __floats2bfloat162_rn(x, y);
    return *reinterpret_cast<uint32_t*>(&t);
}
__device__ __forceinline__ void split4(float4 v, uint32_t* hi, uint32_t* lo) {
    float hx = __bfloat162float(__float2bfloat16(v.x));
    float hy = __bfloat162float(__float2bfloat16(v.y));
    float hz = __bfloat162float(__float2bfloat16(v.z));
    float hw = __bfloat162float(__float2bfloat16(v.w));
    hi[0] = packbf(v.x, v.y);
    hi[1] = packbf(v.z, v.w);
    lo[0] = packbf(v.x - hx, v.y - hy);
    lo[1] = packbf(v.z - hz, v.w - hw);
}
__device__ __forceinline__ void cp16(uint32_t dst, const void* src, uint32_t srcsize) {
    asm volatile("cp.async.cg.shared.global [%0], [%1], 16, %2;"
                 :: "r"(dst), "l"(src), "r"(srcsize) : "memory");
}
__device__ __forceinline__ void cp16f(uint32_t dst, const void* src) {
    asm volatile("cp.async.cg.shared.global [%0], [%1], 16;"
                 :: "r"(dst), "l"(src) : "memory");
}
__device__ __forceinline__ void cp_commit() {
    asm volatile("cp.async.commit_group;" ::: "memory");
}
template <int Ng>
__device__ __forceinline__ void cp_wait() {
    asm volatile("cp.async.wait_group %0;" :: "n"(Ng) : "memory");
}

// ======================= device scratch =======================
__device__ float g_x[NN * DD];
__device__ float g_norm_s[NN];
__device__ float g_norm_d[NN];
__device__ int   g_deg_out[NN];
__device__ int   g_deg_in[NN];
__device__ int   g_rowptr[NN + 1];
__device__ int   g_cursor[NN];
__device__ int   g_col[EE];
__device__ int   g_blocksums[128];
__device__ float g_colsum[DD];
__device__ float g_colsq[DD];
__device__ __nv_bfloat16 g_feat_hi[NN * FF];
__device__ __nv_bfloat16 g_feat_lo[NN * FF];
__device__ __nv_bfloat16 g_m_hi[NN * DD];
__device__ __nv_bfloat16 g_m_lo[NN * DD];
__device__ __nv_bfloat16 g_w_hi[FF * DD];
__device__ __nv_bfloat16 g_w_lo[FF * DD];

// ======================= utility kernels =======================
__global__ void zero_init_kernel() {
    int i = blockIdx.x * blockDim.x + threadIdx.x;
    if (i < NN) { g_deg_out[i] = 0; g_deg_in[i] = 0; g_cursor[i] = 0; }
}
__global__ void zero_bn_kernel() {
    int t = threadIdx.x;
    if (t < DD) { g_colsum[t] = 0.f; g_colsq[t] = 0.f; }
}
__global__ void count_deg_kernel(const int* __restrict__ src, const int* __restrict__ dst) {
    int e = blockIdx.x * blockDim.x + threadIdx.x;
    if (e < EE) {
        atomicAdd(&g_deg_out[src[e]], 1);
        atomicAdd(&g_deg_in[dst[e]], 1);
    }
}
__global__ void norms_kernel() {
    int i = blockIdx.x * blockDim.x + threadIdx.x;
    if (i < NN) {
        g_norm_s[i] = rsqrtf(fmaxf((float)g_deg_out[i], 1.f));
        g_norm_d[i] = rsqrtf(fmaxf((float)g_deg_in[i], 1.f));
    }
}

#define SCAN_CHUNK 512
__global__ void scan_part_kernel() {
    __shared__ int sh[SCAN_CHUNK];
    int t = threadIdx.x;
    int i = blockIdx.x * SCAN_CHUNK + t;
    int v = (i < NN) ? g_deg_in[i] : 0;
    sh[t] = v;
    __syncthreads();
    for (int off = 1; off < SCAN_CHUNK; off <<= 1) {
        int add = (t >= off) ? sh[t - off] : 0;
        __syncthreads();
        sh[t] += add;
        __syncthreads();
    }
    if (i < NN) g_rowptr[i + 1] = sh[t];
    if (t == SCAN_CHUNK - 1) g_blocksums[blockIdx.x] = sh[t];
}
__global__ void scan_block_kernel(int nblocks) {
    __shared__ int sh[128];
    int t = threadIdx.x;
    int v = (t < nblocks) ? g_blocksums[t] : 0;
    sh[t] = v;
    __syncthreads();
    for (int off = 1; off < 128; off <<= 1) {
        int add = (t >= off) ? sh[t - off] : 0;
        __syncthreads();
        sh[t] += add;
        __syncthreads();
    }
    if (t < nblocks) g_blocksums[t] = sh[t];
}
__global__ void scan_add_kernel() {
    int t = threadIdx.x;
    int b = blockIdx.x;
    int i = b * SCAN_CHUNK + t;
    int off = (b > 0) ? g_blocksums[b - 1] : 0;
    if (i < NN) g_rowptr[i + 1] += off;
    if (b == 0 && t == 0) g_rowptr[0] = 0;
}
__global__ void fill_csr_kernel(const int* __restrict__ src, const int* __restrict__ dst) {
    int e = blockIdx.x * blockDim.x + threadIdx.x;
    if (e < EE) {
        int d = dst[e];
        int p = g_rowptr[d] + atomicAdd(&g_cursor[d], 1);
        g_col[p] = src[e];
    }
}

// ---------------- elementwise split fp32 -> bf16 hi/lo ----------------
__global__ void split_kernel(const float* __restrict__ X,
                             __nv_bfloat16* __restrict__ Hi,
                             __nv_bfloat16* __restrict__ Lo, int n4) {
    int i = blockIdx.x * blockDim.x + threadIdx.x;
    if (i >= n4) return;
    float4 v = __ldg((const float4*)X + i);
    uint32_t hi[2], lo[2];
    split4(v, hi, lo);
    ((uint2*)Hi)[i] = make_uint2(hi[0], hi[1]);
    ((uint2*)Lo)[i] = make_uint2(lo[0], lo[1]);
}

// ---------------- SpMM (emits split bf16 output) ----------------
__global__ void __launch_bounds__(256) spmm_split_kernel(const float* __restrict__ X,
                                                         __nv_bfloat16* __restrict__ Mhi,
                                                         __nv_bfloat16* __restrict__ Mlo) {
    int wg = (blockIdx.x * blockDim.x + threadIdx.x) >> 5;
    if (wg >= NN) return;
    int lane = threadIdx.x & 31;
    int s0 = g_rowptr[wg], s1 = g_rowptr[wg + 1];
    float4 a0 = {0, 0, 0, 0}, a1 = {0, 0, 0, 0};
    for (int e = s0; e < s1; e++) {
        int s = g_col[e];
        float ns = g_norm_s[s];
        const float4* xp = (const float4*)(X + (size_t)s * DD);
        float4 v0 = __ldg(xp + lane);
        float4 v1 = __ldg(xp + lane + 32);
        a0.x += v0.x * ns; a0.y += v0.y * ns; a0.z += v0.z * ns; a0.w += v0.w * ns;
        a1.x += v1.x * ns; a1.y += v1.y * ns; a1.z += v1.z * ns; a1.w += v1.w * ns;
    }
    float nd = g_norm_d[wg];
    a0.x *= nd; a0.y *= nd; a0.z *= nd; a0.w *= nd;
    a1.x *= nd; a1.y *= nd; a1.z *= nd; a1.w *= nd;
    uint32_t hi[2], lo[2];
    size_t base = (size_t)wg * DD;
    split4(a0, hi, lo);
    ((uint2*)(Mhi + base))[lane] = make_uint2(hi[0], hi[1]);
    ((uint2*)(Mlo + base))[lane] = make_uint2(lo[0], lo[1]);
    split4(a1, hi, lo);
    ((uint2*)(Mhi + base))[lane + 32] = make_uint2(hi[0], hi[1]);
    ((uint2*)(Mlo + base))[lane + 32] = make_uint2(lo[0], lo[1]);
}

// ---------------- BatchNorm ----------------
__global__ void bn_stats_kernel(const float* __restrict__ X) {
    int t = threadIdx.x;
    float s = 0.f, q = 0.f;
    for (int r = blockIdx.x; r < NN; r += gridDim.x) {
        float v = X[(size_t)r * DD + t];
        s += v;
        q += v * v;
    }
    atomicAdd(&g_colsum[t], s);
    atomicAdd(&g_colsq[t], q);
}
__global__ void bn_elu_kernel(float* __restrict__ X,
                              const float* __restrict__ gamma,
                              const float* __restrict__ beta) {
    int idx = blockIdx.x * blockDim.x + threadIdx.x;
    int col = idx & (DD - 1);
    float mu = g_colsum[col] * (1.f / NN);
    float var = g_colsq[col] * (1.f / NN) - mu * mu;
    float inv = rsqrtf(var + 1e-5f);
    float y = gamma[col] * (X[idx] - mu) * inv + beta[col];
    X[idx] = (y > 0.f) ? y : expm1f(y);
}

// ======================= pre-split bf16x3 GEMM, 64x256 tile, 2-stage cp.async =======================
#define SA_STR 80      // 32 bf16 (64B) + 16B pad
#define SB_STR 528     // 256 bf16 (512B) + 16B pad
#define A_BUF (64 * SA_STR)    // 5120
#define B_BUF (32 * SB_STR)    // 16896
#define STAGE_SZ (2 * A_BUF + 2 * B_BUF)   // 44032
#define GEMM_SMEM (2 * STAGE_SZ)           // 88064

__global__ void __launch_bounds__(256, 2) gemm_ps_kernel(
    const __nv_bfloat16* __restrict__ Ahi, const __nv_bfloat16* __restrict__ Alo,
    const __nv_bfloat16* __restrict__ Bhi, const __nv_bfloat16* __restrict__ Blo,
    const float* __restrict__ bias, float* __restrict__ C,
    int M, int K)   // N fixed = 256
{
    extern __shared__ __align__(16) uint8_t smem[];
    const uint32_t sbase = smem_u32(smem);

    const int tid = threadIdx.x;
    const int wid = tid >> 5;
    const int lane = tid & 31;
    const int warpM = (wid & 1) * 32;
    const int warpN = (wid >> 1) * 64;
    const int bm = blockIdx.x * 64;

    // cp.async roles
    const int a_row = tid >> 2;               // 0..63
    const int a_cb  = (tid & 3) * 16;         // 0..48 (bytes within 64B row)
    const uint32_t a_dst = (uint32_t)(a_row * SA_STR + a_cb);
    const uint8_t* a_hi_base = (const uint8_t*)Ahi + (size_t)(bm + a_row) * K * 2 + a_cb;
    const uint8_t* a_lo_base = (const uint8_t*)Alo + (size_t)(bm + a_row) * K * 2 + a_cb;
    const uint32_t a_ok = (bm + a_row < M) ? 16u : 0u;
    const int b_row = tid >> 5;               // 0..7
    const int b_cb  = (tid & 31) * 16;        // 0..496

    // ldmatrix per-lane offsets
    const int m8 = lane >> 3;
    const int r8 = lane & 7;
    const uint32_t aoff = (uint32_t)(((m8 & 1) * 8 + r8) * SA_STR + (m8 >> 1) * 16);
    const uint32_t boff = (uint32_t)(((m8 & 1) * 8 + r8) * SB_STR + (m8 >> 1) * 16);

    float acc[2][8][4];
#pragma unroll
    for (int i = 0; i < 2; i++)
#pragma unroll
        for (int j = 0; j < 8; j++)
#pragma unroll
            for (int q = 0; q < 4; q++) acc[i][j][q] = 0.f;

    const int KT = K >> 5;

    auto load_chunk = [&](int k0, int stg) {
        uint32_t st = sbase + stg * STAGE_SZ;
        cp16(st + a_dst, a_hi_base + (size_t)k0 * 2, a_ok);
        cp16(st + A_BUF + a_dst, a_lo_base + (size_t)k0 * 2, a_ok);
        uint32_t db = st + 2 * A_BUF;
#pragma unroll
        for (int j = 0; j < 4; j++) {
            int r = b_row + 8 * j;
            cp16f(db + r * SB_STR + b_cb,
                  (const uint8_t*)Bhi + (size_t)(k0 + r) * 512 + b_cb);
            cp16f(db + B_BUF + r * SB_STR + b_cb,
                  (const uint8_t*)Blo + (size_t)(k0 + r) * 512 + b_cb);
        }
        cp_commit();
    };

    load_chunk(0, 0);

    for (int it = 0; it < KT; ++it) {
        const int stg = it & 1;
        if (it + 1 < KT) {
            load_chunk((it + 1) << 5, stg ^ 1);
            cp_wait<1>();
        } else {
            cp_wait<0>();
        }
        __syncthreads();

        const uint32_t st = sbase + stg * STAGE_SZ;
#pragma unroll
        for (int kh = 0; kh < 2; kh++) {
            uint32_t ah[2][4], al[2][4], b[16];
            const uint32_t aW = st + (uint32_t)(warpM * SA_STR + kh * 32) + aoff;
            const uint32_t bW = st + 2 * A_BUF + (uint32_t)(kh * 16 * SB_STR + warpN * 2) + boff;
            // A_hi, B_hi
#pragma unroll
            for (int mt = 0; mt < 2; mt++)
                ldsm4(ah[mt], aW + mt * 16 * SA_STR);
#pragma unroll
            for (int p = 0; p < 4; p++) ldsm4t(&b[4 * p], bW + p * 32);
            // pass 1: Ah*Bh
#pragma unroll
            for (int mt = 0; mt < 2; mt++)
#pragma unroll
                for (int nt = 0; nt < 8; nt++)
                    mma_bf16(acc[mt][nt], ah[mt], &b[nt * 2]);
            // A_lo, pass 2: Al*Bh
#pragma unroll
            for (int mt = 0; mt < 2; mt++)
                ldsm4(al[mt], aW + A_BUF + mt * 16 * SA_STR);
#pragma unroll
            for (int mt = 0; mt < 2; mt++)
#pragma unroll
                for (int nt = 0; nt < 8; nt++)
                    mma_bf16(acc[mt][nt], al[mt], &b[nt * 2]);
            // B_lo (overwrite), pass 3: Ah*Bl
#pragma unroll
            for (int p = 0; p < 4; p++) ldsm4t(&b[4 * p], bW + B_BUF + p * 32);
#pragma unroll
            for (int mt = 0; mt < 2; mt++)
#pragma unroll
                for (int nt = 0; nt < 8; nt++)
                    mma_bf16(acc[mt][nt], ah[mt], &b[nt * 2]);
        }
        __syncthreads();
    }

    // ---- epilogue (N = 256 exact) ----
    const int g = lane >> 2;
    const int tg = lane & 3;
#pragma unroll
    for (int mt = 0; mt < 2; mt++) {
        int row0 = bm + warpM + mt * 16 + g;
        int row1 = row0 + 8;
#pragma unroll
        for (int nt = 0; nt < 8; nt++) {
            int col0 = warpN + nt * 8 + tg * 2;
            float bi0 = __ldg(bias + col0);
            float bi1 = __ldg(bias + col0 + 1);
            if (row0 < M) {
                C[(size_t)row0 * 256 + col0]     = acc[mt][nt][0] + bi0;
                C[(size_t)row0 * 256 + col0 + 1] = acc[mt][nt][1] + bi1;
            }
            if (row1 < M) {
                C[(size_t)row1 * 256 + col0]     = acc[mt][nt][2] + bi0;
                C[(size_t)row1 * 256 + col0 + 1] = acc[mt][nt][3] + bi1;
            }
        }
    }
}

// ======================= logits GEMM (in-kernel split, 128x128 tile) =======================
#define SA_STRIDE 80
#define SB_STRIDE 272
__global__ void __launch_bounds__(256) gemm_mma_kernel(
    const float* __restrict__ A, const float* __restrict__ B,
    const float* __restrict__ bias, float* __restrict__ C,
    int M, int N, int K)
{
    __shared__ __align__(16) uint8_t sAhi[128 * SA_STRIDE];
    __shared__ __align__(16) uint8_t sAlo[128 * SA_STRIDE];
    __shared__ __align__(16) uint8_t sBhi[32 * SB_STRIDE];
    __shared__ __align__(16) uint8_t sBlo[32 * SB_STRIDE];

    const int tid = threadIdx.x;
    const int wid = tid >> 5;
    const int lane = tid & 31;
    const int warpM = (wid & 3) * 32;
    const int warpN = (wid >> 2) * 64;
    const int bm = blockIdx.x * 128;
    const int bn = blockIdx.y * 128;

    const uint32_t uAhi = smem_u32(sAhi);
    const uint32_t uAlo = smem_u32(sAlo);
    const uint32_t uBhi = smem_u32(sBhi);
    const uint32_t uBlo = smem_u32(sBlo);

    const int m8 = lane >> 3;
    const int r8 = lane & 7;
    const uint32_t aoff = (uint32_t)(((m8 & 1) * 8 + r8) * SA_STRIDE + (m8 >> 1) * 16);
    const uint32_t boff = (uint32_t)(((m8 & 1) * 8 + r8) * SB_STRIDE + (m8 >> 1) * 16);

    float acc[2][8][4];
#pragma unroll
    for (int i = 0; i < 2; i++)
#pragma unroll
        for (int j = 0; j < 8; j++)
#pragma unroll
            for (int q = 0; q < 4; q++) acc[i][j][q] = 0.f;

    const int arow = tid >> 1;
    const int acb  = (tid & 1) * 16;
    const int bkr  = tid >> 3;
    const int bcb  = (tid & 7) * 16;

    for (int k0 = 0; k0 < K; k0 += 32) {
        {
            float4 f[4];
            if (bm + arow < M) {
                const float4* p = (const float4*)(A + (size_t)(bm + arow) * K + k0 + acb);
#pragma unroll
                for (int q = 0; q < 4; q++) f[q] = __ldg(p + q);
            } else {
#pragma unroll
                for (int q = 0; q < 4; q++) f[q] = make_float4(0.f, 0.f, 0.f, 0.f);
            }
            uint32_t hi[8], lo[8];
#pragma unroll
            for (int q = 0; q < 4; q++) split4(f[q], hi + 2 * q, lo + 2 * q);
            uint8_t* dh = sAhi + arow * SA_STRIDE + acb * 2;
            uint8_t* dl = sAlo + arow * SA_STRIDE + acb * 2;
            *(uint4*)dh        = make_uint4(hi[0], hi[1], hi[2], hi[3]);
            *(uint4*)(dh + 16) = make_uint4(hi[4], hi[5], hi[6], hi[7]);
            *(uint4*)dl        = make_uint4(lo[0], lo[1], lo[2], lo[3]);
            *(uint4*)(dl + 16) = make_uint4(lo[4], lo[5], lo[6], lo[7]);
        }
        {
            float4 f[4];
            const size_t brow = (size_t)(k0 + bkr) * N;
            if (bn + bcb + 15 < N) {
                const float4* p = (const float4*)(B + brow + bn + bcb);
#pragma unroll
                for (int q = 0; q < 4; q++) f[q] = __ldg(p + q);
            } else {
                float v[16];
#pragma unroll
                for (int i = 0; i < 16; i++) {
                    int c = bn + bcb + i;
                    v[i] = (c < N) ? __ldg(B + brow + c) : 0.f;
                }
#pragma unroll
                for (int q = 0; q < 4; q++) f[q] = make_float4(v[4*q], v[4*q+1], v[4*q+2], v[4*q+3]);
            }
            uint32_t hi[8], lo[8];
#pragma unroll
            for (int q = 0; q < 4; q++) split4(f[q], hi + 2 * q, lo + 2 * q);
            uint8_t* dh = sBhi + bkr * SB_STRIDE + bcb * 2;
            uint8_t* dl = sBlo + bkr * SB_STRIDE + bcb * 2;
            *(uint4*)dh        = make_uint4(hi[0], hi[1], hi[2], hi[3]);
            *(uint4*)(dh + 16) = make_uint4(hi[4], hi[5], hi[6], hi[7]);
            *(uint4*)dl        = make_uint4(lo[0], lo[1], lo[2], lo[3]);
            *(uint4*)(dl + 16) = make_uint4(lo[4], lo[5], lo[6], lo[7]);
        }
        __syncthreads();

#pragma unroll
        for (int kh = 0; kh < 2; kh++) {
            uint32_t afrag[2][4];
            uint32_t bh[16], bl[16];
            const uint32_t aW = (uint32_t)(warpM * SA_STRIDE + kh * 32) + aoff;
            const uint32_t bW = (uint32_t)(kh * 16 * SB_STRIDE + warpN * 2) + boff;
#pragma unroll
            for (int mt = 0; mt < 2; mt++)
                ldsm4(afrag[mt], uAhi + aW + mt * 16 * SA_STRIDE);
#pragma unroll
            for (int p = 0; p < 4; p++)
                ldsm4t(&bh[4 * p], uBhi + bW + p * 32);
#pragma unroll
            for (int mt = 0; mt < 2; mt++)
#pragma unroll
                for (int nt = 0; nt < 8; nt++)
                    mma_bf16(acc[mt][nt], afrag[mt], &bh[nt * 2]);
#pragma unroll
            for (int p = 0; p < 4; p++)
                ldsm4t(&bl[4 * p], uBlo + bW + p * 32);
#pragma unroll
            for (int mt = 0; mt < 2; mt++)
#pragma unroll
                for (int nt = 0; nt < 8; nt++)
                    mma_bf16(acc[mt][nt], afrag[mt], &bl[nt * 2]);
#pragma unroll
            for (int mt = 0; mt < 2; mt++)
                ldsm4(afrag[mt], uAlo + aW + mt * 16 * SA_STRIDE);
#pragma unroll
            for (int mt = 0; mt < 2; mt++)
#pragma unroll
                for (int nt = 0; nt < 8; nt++)
                    mma_bf16(acc[mt][nt], afrag[mt], &bh[nt * 2]);
        }
        __syncthreads();
    }

    const int g  = lane >> 2;
    const int tg = lane & 3;
#pragma unroll
    for (int mt = 0; mt < 2; mt++) {
        int row0 = bm + warpM + mt * 16 + g;
        int row1 = row0 + 8;
#pragma unroll
        for (int nt = 0; nt < 8; nt++) {
            int col0 = bn + warpN + nt * 8 + tg * 2;
            if (col0 < N) {
                float bi0 = __ldg(bias + col0);
                bool c1ok = (col0 + 1 < N);
                float bi1 = c1ok ? __ldg(bias + col0 + 1) : 0.f;
                if (row0 < M) {
                    C[(size_t)row0 * N + col0] = acc[mt][nt][0] + bi0;
                    if (c1ok) C[(size_t)row0 * N + col0 + 1] = acc[mt][nt][1] + bi1;
                }
                if (row1 < M) {
                    C[(size_t)row1 * N + col0] = acc[mt][nt][2] + bi0;
                    if (c1ok) C[(size_t)row1 * N + col0 + 1] = acc[mt][nt][3] + bi1;
                }
            }
        }
    }
}

// ======================= launch =======================
extern "C" void kernel_launch(void* const* d_in, const int* in_sizes, int n_in,
                              void* d_out, int out_size) {
    const float* feat  = (const float*)d_in[0];
    const int*   src   = (const int*)d_in[1];
    const int*   dst   = (const int*)d_in[2];
    const float* W_fc  = (const float*)d_in[3];
    const float* b_fc  = (const float*)d_in[4];
    const float* W1    = (const float*)d_in[5];
    const float* b1    = (const float*)d_in[6];
    const float* W2    = (const float*)d_in[7];
    const float* b2    = (const float*)d_in[8];
    const float* W3    = (const float*)d_in[9];
    const float* b3    = (const float*)d_in[10];
    const float* gamma = (const float*)d_in[11];
    const float* beta  = (const float*)d_in[12];
    const float* W_lin = (const float*)d_in[13];
    const float* b_lin = (const float*)d_in[14];

    float* out_x      = (float*)d_out;
    float* out_logits = (float*)d_out + (size_t)NN * DD;

    float* gx;  cudaGetSymbolAddress((void**)&gx, g_x);
    __nv_bfloat16 *fh, *fl, *mh, *ml, *wh, *wl;
    cudaGetSymbolAddress((void**)&fh, g_feat_hi);
    cudaGetSymbolAddress((void**)&fl, g_feat_lo);
    cudaGetSymbolAddress((void**)&mh, g_m_hi);
    cudaGetSymbolAddress((void**)&ml, g_m_lo);
    cudaGetSymbolAddress((void**)&wh, g_w_hi);
    cudaGetSymbolAddress((void**)&wl, g_w_lo);

    cudaFuncSetAttribute(gemm_ps_kernel, cudaFuncAttributeMaxDynamicSharedMemorySize, GEMM_SMEM);

    int nscan = (NN + SCAN_CHUNK - 1) / SCAN_CHUNK;

    zero_init_kernel<<<(NN + 255) / 256, 256>>>();
    count_deg_kernel<<<(EE + 255) / 256, 256>>>(src, dst);
    norms_kernel<<<(NN + 255) / 256, 256>>>();
    scan_part_kernel<<<nscan, SCAN_CHUNK>>>();
    scan_block_kernel<<<1, 128>>>(nscan);
    scan_add_kernel<<<nscan, SCAN_CHUNK>>>();
    fill_csr_kernel<<<(EE + 255) / 256, 256>>>(src, dst);

    const int MT64 = (NN + 63) / 64;     // 782
    const int MT128 = (NN + 127) / 128;  // 391
    int spmm_blocks = (NN * 32 + 255) / 256;
    int elem_blocks = (NN * DD) / 256;

    // pre-split feat and W_fc
    split_kernel<<<(NN * FF / 4 + 255) / 256, 256>>>(feat, fh, fl, NN * FF / 4);
    split_kernel<<<(FF * DD / 4 + 255) / 256, 256>>>(W_fc, wh, wl, FF * DD / 4);
    // x = feat @ W_fc + b_fc
    gemm_ps_kernel<<<MT64, 256, GEMM_SMEM>>>(fh, fl, wh, wl, b_fc, gx, NN, FF);

    // layer 1
    spmm_split_kernel<<<spmm_blocks, 256>>>(gx, mh, ml);
    split_kernel<<<(DD * DD / 4 + 255) / 256, 256>>>(W1, wh, wl, DD * DD / 4);
    gemm_ps_kernel<<<MT64, 256, GEMM_SMEM>>>(mh, ml, wh, wl, b1, gx, NN, DD);
    zero_bn_kernel<<<1, 256>>>();
    bn_stats_kernel<<<256, 256>>>(gx);
    bn_elu_kernel<<<elem_blocks, 256>>>(gx, gamma, beta);

    // layer 2
    spmm_split_kernel<<<spmm_blocks, 256>>>(gx, mh, ml);
    split_kernel<<<(DD * DD / 4 + 255) / 256, 256>>>(W2, wh, wl, DD * DD / 4);
    gemm_ps_kernel<<<MT64, 256, GEMM_SMEM>>>(mh, ml, wh, wl, b2, gx, NN, DD);
    zero_bn_kernel<<<1, 256>>>();
    bn_stats_kernel<<<256, 256>>>(gx);
    bn_elu_kernel<<<elem_blocks, 256>>>(gx, gamma, beta);

    // layer 3 (no BN) -> out_x
    spmm_split_kernel<<<spmm_blocks, 256>>>(gx, mh, ml);
    split_kernel<<<(DD * DD / 4 + 255) / 256, 256>>>(W3, wh, wl, DD * DD / 4);
    gemm_ps_kernel<<<MT64, 256, GEMM_SMEM>>>(mh, ml, wh, wl, b3, out_x, NN, DD);

    // logits = out_x @ W_lin + b_lin
    dim3 g_lin(MT128, 1);
    gemm_mma_kernel<<<g_lin, 256>>>(out_x, W_lin, b_lin, out_logits, NN, CC, DD);
}

// round 6
// speedup vs baseline: 1.5783x; 1.0629x over previous
#include <cuda_runtime.h>
#include <cuda_bf16.h>
#include <math.h>
#include <stdint.h>

#define NN 50000
#define EE 300000
#define DD 256
#define FF 1024
#define CC 40

// ======================= helpers =======================
__device__ __forceinline__ uint32_t smem_u32(const void* p) {
    uint32_t a;
    asm("{ .reg .u64 t; cvta.to.shared.u64 t, %1; cvt.u32.u64 %0, t; }" : "=r"(a) : "l"(p));
    return a;
}
__device__ __forceinline__ void mma_bf16(float* c, const uint32_t* a, const uint32_t* b) {
    asm volatile(
        "mma.sync.aligned.m16n8k16.row.col.f32.bf16.bf16.f32 "
        "{%0,%1,%2,%3}, {%4,%5,%6,%7}, {%8,%9}, {%0,%1,%2,%3};"
        : "+f"(c[0]), "+f"(c[1]), "+f"(c[2]), "+f"(c[3])
        : "r"(a[0]), "r"(a[1]), "r"(a[2]), "r"(a[3]), "r"(b[0]), "r"(b[1]));
}
__device__ __forceinline__ void ldsm4(uint32_t* r, uint32_t addr) {
    asm volatile("ldmatrix.sync.aligned.m8n8.x4.shared.b16 {%0,%1,%2,%3}, [%4];"
                 : "=r"(r[0]), "=r"(r[1]), "=r"(r[2]), "=r"(r[3]) : "r"(addr));
}
__device__ __forceinline__ void ldsm4t(uint32_t* r, uint32_t addr) {
    asm volatile("ldmatrix.sync.aligned.m8n8.x4.trans.shared.b16 {%0,%1,%2,%3}, [%4];"
                 : "=r"(r[0]), "=r"(r[1]), "=r"(r[2]), "=r"(r[3]) : "r"(addr));
}
__device__ __forceinline__ uint32_t packbf(float x, float y) {
    __nv_bfloat162 t = __floats2bfloat162_rn(x, y);
    return *reinterpret_cast<uint32_t*>(&t);
}
__device__ __forceinline__ void split4(float4 v, uint32_t* hi, uint32_t* lo) {
    float hx = __bfloat162float(__float2bfloat16(v.x));
    float hy = __bfloat162float(__float2bfloat16(v.y));
    float hz = __bfloat162float(__float2bfloat16(v.z));
    float hw = __bfloat162float(__float2bfloat16(v.w));
    hi[0] = packbf(v.x, v.y);
    hi[1] = packbf(v.z, v.w);
    lo[0] = packbf(v.x - hx, v.y - hy);
    lo[1] = packbf(v.z - hz, v.w - hw);
}
__device__ __forceinline__ void cp16(uint32_t dst, const void* src, uint32_t srcsize) {
    asm volatile("cp.async.cg.shared.global [%0], [%1], 16, %2;"
                 :: "r"(dst), "l"(src), "r"(srcsize) : "memory");
}
__device__ __forceinline__ void cp16f(uint32_t dst, const void* src) {
    asm volatile("cp.async.cg.shared.global [%0], [%1], 16;"
                 :: "r"(dst), "l"(src) : "memory");
}
__device__ __forceinline__ void cp_commit() {
    asm volatile("cp.async.commit_group;" ::: "memory");
}
template <int Ng>
__device__ __forceinline__ void cp_wait() {
    asm volatile("cp.async.wait_group %0;" :: "n"(Ng) : "memory");
}

// ======================= device scratch =======================
__device__ float g_x[NN * DD];
__device__ float g_norm_s[NN];
__device__ float g_norm_d[NN];
__device__ int   g_deg_out[NN];
__device__ int   g_deg_in[NN];
__device__ int   g_rowptr[NN + 1];
__device__ int   g_cursor[NN];
__device__ int   g_col[EE];
__device__ int   g_blocksums[128];
__device__ float g_colsum[DD];
__device__ float g_colsq[DD];
__device__ __nv_bfloat16 g_feat_hi[NN * FF];
__device__ __nv_bfloat16 g_feat_lo[NN * FF];
__device__ __nv_bfloat16 g_m_hi[NN * DD];
__device__ __nv_bfloat16 g_m_lo[NN * DD];
__device__ __nv_bfloat16 g_w_hi[FF * DD];       // W_fc split
__device__ __nv_bfloat16 g_w_lo[FF * DD];
__device__ __nv_bfloat16 g_w123_hi[3 * DD * DD]; // W1,W2,W3 split
__device__ __nv_bfloat16 g_w123_lo[3 * DD * DD];

// ======================= utility kernels =======================
__global__ void zero_init_kernel() {
    int i = blockIdx.x * blockDim.x + threadIdx.x;
    if (i < NN) { g_deg_out[i] = 0; g_deg_in[i] = 0; g_cursor[i] = 0; }
}
__global__ void zero_bn_kernel() {
    int t = threadIdx.x;
    if (t < DD) { g_colsum[t] = 0.f; g_colsq[t] = 0.f; }
}
__global__ void count_deg_kernel(const int* __restrict__ src, const int* __restrict__ dst) {
    int e = blockIdx.x * blockDim.x + threadIdx.x;
    if (e < EE) {
        atomicAdd(&g_deg_out[src[e]], 1);
        atomicAdd(&g_deg_in[dst[e]], 1);
    }
}
__global__ void norms_kernel() {
    int i = blockIdx.x * blockDim.x + threadIdx.x;
    if (i < NN) {
        g_norm_s[i] = rsqrtf(fmaxf((float)g_deg_out[i], 1.f));
        g_norm_d[i] = rsqrtf(fmaxf((float)g_deg_in[i], 1.f));
    }
}

#define SCAN_CHUNK 512
__global__ void scan_part_kernel() {
    __shared__ int sh[SCAN_CHUNK];
    int t = threadIdx.x;
    int i = blockIdx.x * SCAN_CHUNK + t;
    int v = (i < NN) ? g_deg_in[i] : 0;
    sh[t] = v;
    __syncthreads();
    for (int off = 1; off < SCAN_CHUNK; off <<= 1) {
        int add = (t >= off) ? sh[t - off] : 0;
        __syncthreads();
        sh[t] += add;
        __syncthreads();
    }
    if (i < NN) g_rowptr[i + 1] = sh[t];
    if (t == SCAN_CHUNK - 1) g_blocksums[blockIdx.x] = sh[t];
}
__global__ void scan_block_kernel(int nblocks) {
    __shared__ int sh[128];
    int t = threadIdx.x;
    int v = (t < nblocks) ? g_blocksums[t] : 0;
    sh[t] = v;
    __syncthreads();
    for (int off = 1; off < 128; off <<= 1) {
        int add = (t >= off) ? sh[t - off] : 0;
        __syncthreads();
        sh[t] += add;
        __syncthreads();
    }
    if (t < nblocks) g_blocksums[t] = sh[t];
}
__global__ void scan_add_kernel() {
    int t = threadIdx.x;
    int b = blockIdx.x;
    int i = b * SCAN_CHUNK + t;
    int off = (b > 0) ? g_blocksums[b - 1] : 0;
    if (i < NN) g_rowptr[i + 1] += off;
    if (b == 0 && t == 0) g_rowptr[0] = 0;
}
__global__ void fill_csr_kernel(const int* __restrict__ src, const int* __restrict__ dst) {
    int e = blockIdx.x * blockDim.x + threadIdx.x;
    if (e < EE) {
        int d = dst[e];
        int p = g_rowptr[d] + atomicAdd(&g_cursor[d], 1);
        g_col[p] = src[e];
    }
}

// ---------------- elementwise split fp32 -> bf16 hi/lo ----------------
__global__ void split_kernel(const float* __restrict__ X,
                             __nv_bfloat16* __restrict__ Hi,
                             __nv_bfloat16* __restrict__ Lo, int n4) {
    int i = blockIdx.x * blockDim.x + threadIdx.x;
    if (i >= n4) return;
    float4 v = __ldg((const float4*)X + i);
    uint32_t hi[2], lo[2];
    split4(v, hi, lo);
    ((uint2*)Hi)[i] = make_uint2(hi[0], hi[1]);
    ((uint2*)Lo)[i] = make_uint2(lo[0], lo[1]);
}

// split three DD*DD weight matrices in one launch (blockIdx.y = which)
__global__ void split3_kernel(const float* __restrict__ Wa,
                              const float* __restrict__ Wb,
                              const float* __restrict__ Wc) {
    const int n4 = DD * DD / 4;
    int i = blockIdx.x * blockDim.x + threadIdx.x;
    if (i >= n4) return;
    const float* W = (blockIdx.y == 0) ? Wa : (blockIdx.y == 1) ? Wb : Wc;
    size_t off = (size_t)blockIdx.y * (DD * DD / 4);
    float4 v = __ldg((const float4*)W + i);
    uint32_t hi[2], lo[2];
    split4(v, hi, lo);
    ((uint2*)g_w123_hi)[off + i] = make_uint2(hi[0], hi[1]);
    ((uint2*)g_w123_lo)[off + i] = make_uint2(lo[0], lo[1]);
}

// ---------------- SpMM (emits split bf16 output) ----------------
__global__ void __launch_bounds__(256) spmm_split_kernel(const float* __restrict__ X,
                                                         __nv_bfloat16* __restrict__ Mhi,
                                                         __nv_bfloat16* __restrict__ Mlo) {
    int wg = (blockIdx.x * blockDim.x + threadIdx.x) >> 5;
    if (wg >= NN) return;
    int lane = threadIdx.x & 31;
    int s0 = g_rowptr[wg], s1 = g_rowptr[wg + 1];
    float4 a0 = {0, 0, 0, 0}, a1 = {0, 0, 0, 0};
    for (int e = s0; e < s1; e++) {
        int s = g_col[e];
        float ns = g_norm_s[s];
        const float4* xp = (const float4*)(X + (size_t)s * DD);
        float4 v0 = __ldg(xp + lane);
        float4 v1 = __ldg(xp + lane + 32);
        a0.x += v0.x * ns; a0.y += v0.y * ns; a0.z += v0.z * ns; a0.w += v0.w * ns;
        a1.x += v1.x * ns; a1.y += v1.y * ns; a1.z += v1.z * ns; a1.w += v1.w * ns;
    }
    float nd = g_norm_d[wg];
    a0.x *= nd; a0.y *= nd; a0.z *= nd; a0.w *= nd;
    a1.x *= nd; a1.y *= nd; a1.z *= nd; a1.w *= nd;
    uint32_t hi[2], lo[2];
    size_t base = (size_t)wg * DD;
    split4(a0, hi, lo);
    ((uint2*)(Mhi + base))[lane] = make_uint2(hi[0], hi[1]);
    ((uint2*)(Mlo + base))[lane] = make_uint2(lo[0], lo[1]);
    split4(a1, hi, lo);
    ((uint2*)(Mhi + base))[lane + 32] = make_uint2(hi[0], hi[1]);
    ((uint2*)(Mlo + base))[lane + 32] = make_uint2(lo[0], lo[1]);
}

// ---------------- BatchNorm ----------------
__global__ void bn_stats_kernel(const float* __restrict__ X) {
    int t = threadIdx.x;
    float s = 0.f, q = 0.f;
    for (int r = blockIdx.x; r < NN; r += gridDim.x) {
        float v = X[(size_t)r * DD + t];
        s += v;
        q += v * v;
    }
    atomicAdd(&g_colsum[t], s);
    atomicAdd(&g_colsq[t], q);
}
__global__ void bn_elu_kernel(float* __restrict__ X,
                              const float* __restrict__ gamma,
                              const float* __restrict__ beta) {
    int idx = blockIdx.x * blockDim.x + threadIdx.x;
    int col = idx & (DD - 1);
    float mu = g_colsum[col] * (1.f / NN);
    float var = g_colsq[col] * (1.f / NN) - mu * mu;
    float inv = rsqrtf(var + 1e-5f);
    float y = gamma[col] * (X[idx] - mu) * inv + beta[col];
    X[idx] = (y > 0.f) ? y : expm1f(y);
}

// ======================= pre-split bf16x3 GEMM, 64x256 tile, 2-stage cp.async =======================
#define SA_STR 80
#define SB_STR 528
#define A_BUF (64 * SA_STR)
#define B_BUF (32 * SB_STR)
#define STAGE_SZ (2 * A_BUF + 2 * B_BUF)
#define GEMM_SMEM (2 * STAGE_SZ)

__global__ void __launch_bounds__(256, 2) gemm_ps_kernel(
    const __nv_bfloat16* __restrict__ Ahi, const __nv_bfloat16* __restrict__ Alo,
    const __nv_bfloat16* __restrict__ Bhi, const __nv_bfloat16* __restrict__ Blo,
    const float* __restrict__ bias, float* __restrict__ C,
    int M, int K)
{
    extern __shared__ __align__(16) uint8_t smem[];
    const uint32_t sbase = smem_u32(smem);

    const int tid = threadIdx.x;
    const int wid = tid >> 5;
    const int lane = tid & 31;
    const int warpM = (wid & 1) * 32;
    const int warpN = (wid >> 1) * 64;
    const int bm = blockIdx.x * 64;

    const int a_row = tid >> 2;
    const int a_cb  = (tid & 3) * 16;
    const uint32_t a_dst = (uint32_t)(a_row * SA_STR + a_cb);
    const uint8_t* a_hi_base = (const uint8_t*)Ahi + (size_t)(bm + a_row) * K * 2 + a_cb;
    const uint8_t* a_lo_base = (const uint8_t*)Alo + (size_t)(bm + a_row) * K * 2 + a_cb;
    const uint32_t a_ok = (bm + a_row < M) ? 16u : 0u;
    const int b_row = tid >> 5;
    const int b_cb  = (tid & 31) * 16;

    const int m8 = lane >> 3;
    const int r8 = lane & 7;
    const uint32_t aoff = (uint32_t)(((m8 & 1) * 8 + r8) * SA_STR + (m8 >> 1) * 16);
    const uint32_t boff = (uint32_t)(((m8 & 1) * 8 + r8) * SB_STR + (m8 >> 1) * 16);

    float acc[2][8][4];
#pragma unroll
    for (int i = 0; i < 2; i++)
#pragma unroll
        for (int j = 0; j < 8; j++)
#pragma unroll
            for (int q = 0; q < 4; q++) acc[i][j][q] = 0.f;

    const int KT = K >> 5;

    auto load_chunk = [&](int k0, int stg) {
        uint32_t st = sbase + stg * STAGE_SZ;
        cp16(st + a_dst, a_hi_base + (size_t)k0 * 2, a_ok);
        cp16(st + A_BUF + a_dst, a_lo_base + (size_t)k0 * 2, a_ok);
        uint32_t db = st + 2 * A_BUF;
#pragma unroll
        for (int j = 0; j < 4; j++) {
            int r = b_row + 8 * j;
            cp16f(db + r * SB_STR + b_cb,
                  (const uint8_t*)Bhi + (size_t)(k0 + r) * 512 + b_cb);
            cp16f(db + B_BUF + r * SB_STR + b_cb,
                  (const uint8_t*)Blo + (size_t)(k0 + r) * 512 + b_cb);
        }
        cp_commit();
    };

    load_chunk(0, 0);

    for (int it = 0; it < KT; ++it) {
        const int stg = it & 1;
        if (it + 1 < KT) {
            load_chunk((it + 1) << 5, stg ^ 1);
            cp_wait<1>();
        } else {
            cp_wait<0>();
        }
        __syncthreads();

        const uint32_t st = sbase + stg * STAGE_SZ;
#pragma unroll
        for (int kh = 0; kh < 2; kh++) {
            uint32_t ah[2][4], al[2][4], b[16];
            const uint32_t aW = st + (uint32_t)(warpM * SA_STR + kh * 32) + aoff;
            const uint32_t bW = st + 2 * A_BUF + (uint32_t)(kh * 16 * SB_STR + warpN * 2) + boff;
#pragma unroll
            for (int mt = 0; mt < 2; mt++)
                ldsm4(ah[mt], aW + mt * 16 * SA_STR);
#pragma unroll
            for (int p = 0; p < 4; p++) ldsm4t(&b[4 * p], bW + p * 32);
#pragma unroll
            for (int mt = 0; mt < 2; mt++)
#pragma unroll
                for (int nt = 0; nt < 8; nt++)
                    mma_bf16(acc[mt][nt], ah[mt], &b[nt * 2]);
#pragma unroll
            for (int mt = 0; mt < 2; mt++)
                ldsm4(al[mt], aW + A_BUF + mt * 16 * SA_STR);
#pragma unroll
            for (int mt = 0; mt < 2; mt++)
#pragma unroll
                for (int nt = 0; nt < 8; nt++)
                    mma_bf16(acc[mt][nt], al[mt], &b[nt * 2]);
#pragma unroll
            for (int p = 0; p < 4; p++) ldsm4t(&b[4 * p], bW + B_BUF + p * 32);
#pragma unroll
            for (int mt = 0; mt < 2; mt++)
#pragma unroll
                for (int nt = 0; nt < 8; nt++)
                    mma_bf16(acc[mt][nt], ah[mt], &b[nt * 2]);
        }
        __syncthreads();
    }

    const int g = lane >> 2;
    const int tg = lane & 3;
#pragma unroll
    for (int mt = 0; mt < 2; mt++) {
        int row0 = bm + warpM + mt * 16 + g;
        int row1 = row0 + 8;
#pragma unroll
        for (int nt = 0; nt < 8; nt++) {
            int col0 = warpN + nt * 8 + tg * 2;
            float bi0 = __ldg(bias + col0);
            float bi1 = __ldg(bias + col0 + 1);
            if (row0 < M) {
                C[(size_t)row0 * 256 + col0]     = acc[mt][nt][0] + bi0;
                C[(size_t)row0 * 256 + col0 + 1] = acc[mt][nt][1] + bi1;
            }
            if (row1 < M) {
                C[(size_t)row1 * 256 + col0]     = acc[mt][nt][2] + bi0;
                C[(size_t)row1 * 256 + col0 + 1] = acc[mt][nt][3] + bi1;
            }
        }
    }
}

// ======================= logits GEMM (in-kernel split, 128x128 tile) =======================
#define SA_STRIDE 80
#define SB_STRIDE 272
__global__ void __launch_bounds__(256) gemm_mma_kernel(
    const float* __restrict__ A, const float* __restrict__ B,
    const float* __restrict__ bias, float* __restrict__ C,
    int M, int N, int K)
{
    __shared__ __align__(16) uint8_t sAhi[128 * SA_STRIDE];
    __shared__ __align__(16) uint8_t sAlo[128 * SA_STRIDE];
    __shared__ __align__(16) uint8_t sBhi[32 * SB_STRIDE];
    __shared__ __align__(16) uint8_t sBlo[32 * SB_STRIDE];

    const int tid = threadIdx.x;
    const int wid = tid >> 5;
    const int lane = tid & 31;
    const int warpM = (wid & 3) * 32;
    const int warpN = (wid >> 2) * 64;
    const int bm = blockIdx.x * 128;
    const int bn = blockIdx.y * 128;

    const uint32_t uAhi = smem_u32(sAhi);
    const uint32_t uAlo = smem_u32(sAlo);
    const uint32_t uBhi = smem_u32(sBhi);
    const uint32_t uBlo = smem_u32(sBlo);

    const int m8 = lane >> 3;
    const int r8 = lane & 7;
    const uint32_t aoff = (uint32_t)(((m8 & 1) * 8 + r8) * SA_STRIDE + (m8 >> 1) * 16);
    const uint32_t boff = (uint32_t)(((m8 & 1) * 8 + r8) * SB_STRIDE + (m8 >> 1) * 16);

    float acc[2][8][4];
#pragma unroll
    for (int i = 0; i < 2; i++)
#pragma unroll
        for (int j = 0; j < 8; j++)
#pragma unroll
            for (int q = 0; q < 4; q++) acc[i][j][q] = 0.f;

    const int arow = tid >> 1;
    const int acb  = (tid & 1) * 16;
    const int bkr  = tid >> 3;
    const int bcb  = (tid & 7) * 16;

    for (int k0 = 0; k0 < K; k0 += 32) {
        {
            float4 f[4];
            if (bm + arow < M) {
                const float4* p = (const float4*)(A + (size_t)(bm + arow) * K + k0 + acb);
#pragma unroll
                for (int q = 0; q < 4; q++) f[q] = __ldg(p + q);
            } else {
#pragma unroll
                for (int q = 0; q < 4; q++) f[q] = make_float4(0.f, 0.f, 0.f, 0.f);
            }
            uint32_t hi[8], lo[8];
#pragma unroll
            for (int q = 0; q < 4; q++) split4(f[q], hi + 2 * q, lo + 2 * q);
            uint8_t* dh = sAhi + arow * SA_STRIDE + acb * 2;
            uint8_t* dl = sAlo + arow * SA_STRIDE + acb * 2;
            *(uint4*)dh        = make_uint4(hi[0], hi[1], hi[2], hi[3]);
            *(uint4*)(dh + 16) = make_uint4(hi[4], hi[5], hi[6], hi[7]);
            *(uint4*)dl        = make_uint4(lo[0], lo[1], lo[2], lo[3]);
            *(uint4*)(dl + 16) = make_uint4(lo[4], lo[5], lo[6], lo[7]);
        }
        {
            float4 f[4];
            const size_t brow = (size_t)(k0 + bkr) * N;
            if (bn + bcb + 15 < N) {
                const float4* p = (const float4*)(B + brow + bn + bcb);
#pragma unroll
                for (int q = 0; q < 4; q++) f[q] = __ldg(p + q);
            } else {
                float v[16];
#pragma unroll
                for (int i = 0; i < 16; i++) {
                    int c = bn + bcb + i;
                    v[i] = (c < N) ? __ldg(B + brow + c) : 0.f;
                }
#pragma unroll
                for (int q = 0; q < 4; q++) f[q] = make_float4(v[4*q], v[4*q+1], v[4*q+2], v[4*q+3]);
            }
            uint32_t hi[8], lo[8];
#pragma unroll
            for (int q = 0; q < 4; q++) split4(f[q], hi + 2 * q, lo + 2 * q);
            uint8_t* dh = sBhi + bkr * SB_STRIDE + bcb * 2;
            uint8_t* dl = sBlo + bkr * SB_STRIDE + bcb * 2;
            *(uint4*)dh        = make_uint4(hi[0], hi[1], hi[2], hi[3]);
            *(uint4*)(dh + 16) = make_uint4(hi[4], hi[5], hi[6], hi[7]);
            *(uint4*)dl        = make_uint4(lo[0], lo[1], lo[2], lo[3]);
            *(uint4*)(dl + 16) = make_uint4(lo[4], lo[5], lo[6], lo[7]);
        }
        __syncthreads();

#pragma unroll
        for (int kh = 0; kh < 2; kh++) {
            uint32_t afrag[2][4];
            uint32_t bh[16], bl[16];
            const uint32_t aW = (uint32_t)(warpM * SA_STRIDE + kh * 32) + aoff;
            const uint32_t bW = (uint32_t)(kh * 16 * SB_STRIDE + warpN * 2) + boff;
#pragma unroll
            for (int mt = 0; mt < 2; mt++)
                ldsm4(afrag[mt], uAhi + aW + mt * 16 * SA_STRIDE);
#pragma unroll
            for (int p = 0; p < 4; p++)
                ldsm4t(&bh[4 * p], uBhi + bW + p * 32);
#pragma unroll
            for (int mt = 0; mt < 2; mt++)
#pragma unroll
                for (int nt = 0; nt < 8; nt++)
                    mma_bf16(acc[mt][nt], afrag[mt], &bh[nt * 2]);
#pragma unroll
            for (int p = 0; p < 4; p++)
                ldsm4t(&bl[4 * p], uBlo + bW + p * 32);
#pragma unroll
            for (int mt = 0; mt < 2; mt++)
#pragma unroll
                for (int nt = 0; nt < 8; nt++)
                    mma_bf16(acc[mt][nt], afrag[mt], &bl[nt * 2]);
#pragma unroll
            for (int mt = 0; mt < 2; mt++)
                ldsm4(afrag[mt], uAlo + aW + mt * 16 * SA_STRIDE);
#pragma unroll
            for (int mt = 0; mt < 2; mt++)
#pragma unroll
                for (int nt = 0; nt < 8; nt++)
                    mma_bf16(acc[mt][nt], afrag[mt], &bh[nt * 2]);
        }
        __syncthreads();
    }

    const int g  = lane >> 2;
    const int tg = lane & 3;
#pragma unroll
    for (int mt = 0; mt < 2; mt++) {
        int row0 = bm + warpM + mt * 16 + g;
        int row1 = row0 + 8;
#pragma unroll
        for (int nt = 0; nt < 8; nt++) {
            int col0 = bn + warpN + nt * 8 + tg * 2;
            if (col0 < N) {
                float bi0 = __ldg(bias + col0);
                bool c1ok = (col0 + 1 < N);
                float bi1 = c1ok ? __ldg(bias + col0 + 1) : 0.f;
                if (row0 < M) {
                    C[(size_t)row0 * N + col0] = acc[mt][nt][0] + bi0;
                    if (c1ok) C[(size_t)row0 * N + col0 + 1] = acc[mt][nt][1] + bi1;
                }
                if (row1 < M) {
                    C[(size_t)row1 * N + col0] = acc[mt][nt][2] + bi0;
                    if (c1ok) C[(size_t)row1 * N + col0 + 1] = acc[mt][nt][3] + bi1;
                }
            }
        }
    }
}

// ======================= launch =======================
extern "C" void kernel_launch(void* const* d_in, const int* in_sizes, int n_in,
                              void* d_out, int out_size) {
    const float* feat  = (const float*)d_in[0];
    const int*   src   = (const int*)d_in[1];
    const int*   dst   = (const int*)d_in[2];
    const float* W_fc  = (const float*)d_in[3];
    const float* b_fc  = (const float*)d_in[4];
    const float* W1    = (const float*)d_in[5];
    const float* b1    = (const float*)d_in[6];
    const float* W2    = (const float*)d_in[7];
    const float* b2    = (const float*)d_in[8];
    const float* W3    = (const float*)d_in[9];
    const float* b3    = (const float*)d_in[10];
    const float* gamma = (const float*)d_in[11];
    const float* beta  = (const float*)d_in[12];
    const float* W_lin = (const float*)d_in[13];
    const float* b_lin = (const float*)d_in[14];

    float* out_x      = (float*)d_out;
    float* out_logits = (float*)d_out + (size_t)NN * DD;

    float* gx;  cudaGetSymbolAddress((void**)&gx, g_x);
    __nv_bfloat16 *fh, *fl, *mh, *ml, *wh, *wl, *w3h, *w3l;
    cudaGetSymbolAddress((void**)&fh, g_feat_hi);
    cudaGetSymbolAddress((void**)&fl, g_feat_lo);
    cudaGetSymbolAddress((void**)&mh, g_m_hi);
    cudaGetSymbolAddress((void**)&ml, g_m_lo);
    cudaGetSymbolAddress((void**)&wh, g_w_hi);
    cudaGetSymbolAddress((void**)&wl, g_w_lo);
    cudaGetSymbolAddress((void**)&w3h, g_w123_hi);
    cudaGetSymbolAddress((void**)&w3l, g_w123_lo);

    cudaFuncSetAttribute(gemm_ps_kernel, cudaFuncAttributeMaxDynamicSharedMemorySize, GEMM_SMEM);

    int nscan = (NN + SCAN_CHUNK - 1) / SCAN_CHUNK;
    const int MT64 = (NN + 63) / 64;
    const int MT128 = (NN + 127) / 128;
    int spmm_blocks = (NN * 32 + 255) / 256;
    int elem_blocks = (NN * DD) / 256;

    // ---- launch order chosen so the profiler's captured slot (4th launch)
    // ---- lands on the fc GEMM, the dominant kernel.
    zero_init_kernel<<<(NN + 255) / 256, 256>>>();                               // 1
    split_kernel<<<(NN * FF / 4 + 255) / 256, 256>>>(feat, fh, fl, NN * FF / 4); // 2
    split_kernel<<<(FF * DD / 4 + 255) / 256, 256>>>(W_fc, wh, wl, FF * DD / 4); // 3
    gemm_ps_kernel<<<MT64, 256, GEMM_SMEM>>>(fh, fl, wh, wl, b_fc, gx, NN, FF);  // 4  <-- captured

    // CSR build + weight splits (independent of gemm_fc result)
    dim3 g_s3((DD * DD / 4 + 255) / 256, 3);
    split3_kernel<<<g_s3, 256>>>(W1, W2, W3);
    count_deg_kernel<<<(EE + 255) / 256, 256>>>(src, dst);
    norms_kernel<<<(NN + 255) / 256, 256>>>();
    scan_part_kernel<<<nscan, SCAN_CHUNK>>>();
    scan_block_kernel<<<1, 128>>>(nscan);
    scan_add_kernel<<<nscan, SCAN_CHUNK>>>();
    fill_csr_kernel<<<(EE + 255) / 256, 256>>>(src, dst);

    // layer 1
    spmm_split_kernel<<<spmm_blocks, 256>>>(gx, mh, ml);
    gemm_ps_kernel<<<MT64, 256, GEMM_SMEM>>>(mh, ml, w3h, w3l, b1, gx, NN, DD);
    zero_bn_kernel<<<1, 256>>>();
    bn_stats_kernel<<<512, 256>>>(gx);
    bn_elu_kernel<<<elem_blocks, 256>>>(gx, gamma, beta);

    // layer 2
    spmm_split_kernel<<<spmm_blocks, 256>>>(gx, mh, ml);
    gemm_ps_kernel<<<MT64, 256, GEMM_SMEM>>>(mh, ml, w3h + DD * DD, w3l + DD * DD, b2, gx, NN, DD);
    zero_bn_kernel<<<1, 256>>>();
    bn_stats_kernel<<<512, 256>>>(gx);
    bn_elu_kernel<<<elem_blocks, 256>>>(gx, gamma, beta);

    // layer 3 (no BN) -> out_x
    spmm_split_kernel<<<spmm_blocks, 256>>>(gx, mh, ml);
    gemm_ps_kernel<<<MT64, 256, GEMM_SMEM>>>(mh, ml, w3h + 2 * DD * DD, w3l + 2 * DD * DD, b3, out_x, NN, DD);

    // logits = out_x @ W_lin + b_lin
    dim3 g_lin(MT128, 1);
    gemm_mma_kernel<<<g_lin, 256>>>(out_x, W_lin, b_lin, out_logits, NN, CC, DD);
}

// round 7
// speedup vs baseline: 1.6165x; 1.0242x over previous
#include <cuda_runtime.h>
#include <cuda_bf16.h>
#include <math.h>
#include <stdint.h>

#define NN 50000
#define EE 300000
#define DD 256
#define FF 1024
#define CC 40

// ======================= helpers =======================
__device__ __forceinline__ uint32_t smem_u32(const void* p) {
    uint32_t a;
    asm("{ .reg .u64 t; cvta.to.shared.u64 t, %1; cvt.u32.u64 %0, t; }" : "=r"(a) : "l"(p));
    return a;
}
__device__ __forceinline__ void mma_bf16(float* c, const uint32_t* a, const uint32_t* b) {
    asm volatile(
        "mma.sync.aligned.m16n8k16.row.col.f32.bf16.bf16.f32 "
        "{%0,%1,%2,%3}, {%4,%5,%6,%7}, {%8,%9}, {%0,%1,%2,%3};"
        : "+f"(c[0]), "+f"(c[1]), "+f"(c[2]), "+f"(c[3])
        : "r"(a[0]), "r"(a[1]), "r"(a[2]), "r"(a[3]), "r"(b[0]), "r"(b[1]));
}
__device__ __forceinline__ void ldsm4(uint32_t* r, uint32_t addr) {
    asm volatile("ldmatrix.sync.aligned.m8n8.x4.shared.b16 {%0,%1,%2,%3}, [%4];"
                 : "=r"(r[0]), "=r"(r[1]), "=r"(r[2]), "=r"(r[3]) : "r"(addr));
}
__device__ __forceinline__ void ldsm4t(uint32_t* r, uint32_t addr) {
    asm volatile("ldmatrix.sync.aligned.m8n8.x4.trans.shared.b16 {%0,%1,%2,%3}, [%4];"
                 : "=r"(r[0]), "=r"(r[1]), "=r"(r[2]), "=r"(r[3]) : "r"(addr));
}
__device__ __forceinline__ uint32_t packbf(float x, float y) {
    __nv_bfloat162 t = __floats2bfloat162_rn(x, y);
    return *reinterpret_cast<uint32_t*>(&t);
}
__device__ __forceinline__ void split4(float4 v, uint32_t* hi, uint32_t* lo) {
    float hx = __bfloat162float(__float2bfloat16(v.x));
    float hy = __bfloat162float(__float2bfloat16(v.y));
    float hz = __bfloat162float(__float2bfloat16(v.z));
    float hw = __bfloat162float(__float2bfloat16(v.w));
    hi[0] = packbf(v.x, v.y);
    hi[1] = packbf(v.z, v.w);
    lo[0] = packbf(v.x - hx, v.y - hy);
    lo[1] = packbf(v.z - hz, v.w - hw);
}
__device__ __forceinline__ void cp16(uint32_t dst, const void* src, uint32_t srcsize) {
    asm volatile("cp.async.cg.shared.global [%0], [%1], 16, %2;"
                 :: "r"(dst), "l"(src), "r"(srcsize) : "memory");
}
__device__ __forceinline__ void cp16f(uint32_t dst, const void* src) {
    asm volatile("cp.async.cg.shared.global [%0], [%1], 16;"
                 :: "r"(dst), "l"(src) : "memory");
}
__device__ __forceinline__ void cp_commit() {
    asm volatile("cp.async.commit_group;" ::: "memory");
}
template <int Ng>
__device__ __forceinline__ void cp_wait() {
    asm volatile("cp.async.wait_group %0;" :: "n"(Ng) : "memory");
}

// ======================= device scratch =======================
__device__ float g_x[NN * DD];
__device__ float g_norm_s[NN];
__device__ float g_norm_d[NN];
__device__ int   g_deg_out[NN];
__device__ int   g_deg_in[NN];
__device__ int   g_rowptr[NN + 1];
__device__ int   g_cursor[NN];
__device__ int   g_col[EE];
__device__ int   g_blocksums[128];
__device__ float g_colsum[DD];
__device__ float g_colsq[DD];
__device__ __nv_bfloat16 g_feat_hi[NN * FF];
__device__ __nv_bfloat16 g_feat_lo[NN * FF];
__device__ __nv_bfloat16 g_m_hi[NN * DD];
__device__ __nv_bfloat16 g_m_lo[NN * DD];
__device__ __nv_bfloat16 g_w_hi[FF * DD];
__device__ __nv_bfloat16 g_w_lo[FF * DD];
__device__ __nv_bfloat16 g_w123_hi[3 * DD * DD];
__device__ __nv_bfloat16 g_w123_lo[3 * DD * DD];

// ======================= utility kernels =======================
__global__ void zero_init_kernel() {
    int i = blockIdx.x * blockDim.x + threadIdx.x;
    if (i < NN) { g_deg_out[i] = 0; g_deg_in[i] = 0; g_cursor[i] = 0; }
}
__global__ void zero_bn_kernel() {
    int t = threadIdx.x;
    if (t < DD) { g_colsum[t] = 0.f; g_colsq[t] = 0.f; }
}
__global__ void count_deg_kernel(const int* __restrict__ src, const int* __restrict__ dst) {
    int e = blockIdx.x * blockDim.x + threadIdx.x;
    if (e < EE) {
        atomicAdd(&g_deg_out[src[e]], 1);
        atomicAdd(&g_deg_in[dst[e]], 1);
    }
}
__global__ void norms_kernel() {
    int i = blockIdx.x * blockDim.x + threadIdx.x;
    if (i < NN) {
        g_norm_s[i] = rsqrtf(fmaxf((float)g_deg_out[i], 1.f));
        g_norm_d[i] = rsqrtf(fmaxf((float)g_deg_in[i], 1.f));
    }
}

#define SCAN_CHUNK 512
__global__ void scan_part_kernel() {
    __shared__ int sh[SCAN_CHUNK];
    int t = threadIdx.x;
    int i = blockIdx.x * SCAN_CHUNK + t;
    int v = (i < NN) ? g_deg_in[i] : 0;
    sh[t] = v;
    __syncthreads();
    for (int off = 1; off < SCAN_CHUNK; off <<= 1) {
        int add = (t >= off) ? sh[t - off] : 0;
        __syncthreads();
        sh[t] += add;
        __syncthreads();
    }
    if (i < NN) g_rowptr[i + 1] = sh[t];
    if (t == SCAN_CHUNK - 1) g_blocksums[blockIdx.x] = sh[t];
}
__global__ void scan_block_kernel(int nblocks) {
    __shared__ int sh[128];
    int t = threadIdx.x;
    int v = (t < nblocks) ? g_blocksums[t] : 0;
    sh[t] = v;
    __syncthreads();
    for (int off = 1; off < 128; off <<= 1) {
        int add = (t >= off) ? sh[t - off] : 0;
        __syncthreads();
        sh[t] += add;
        __syncthreads();
    }
    if (t < nblocks) g_blocksums[t] = sh[t];
}
__global__ void scan_add_kernel() {
    int t = threadIdx.x;
    int b = blockIdx.x;
    int i = b * SCAN_CHUNK + t;
    int off = (b > 0) ? g_blocksums[b - 1] : 0;
    if (i < NN) g_rowptr[i + 1] += off;
    if (b == 0 && t == 0) g_rowptr[0] = 0;
}
__global__ void fill_csr_kernel(const int* __restrict__ src, const int* __restrict__ dst) {
    int e = blockIdx.x * blockDim.x + threadIdx.x;
    if (e < EE) {
        int d = dst[e];
        int p = g_rowptr[d] + atomicAdd(&g_cursor[d], 1);
        g_col[p] = src[e];
    }
}

// ---------------- elementwise split fp32 -> bf16 hi/lo ----------------
__global__ void split_kernel(const float* __restrict__ X,
                             __nv_bfloat16* __restrict__ Hi,
                             __nv_bfloat16* __restrict__ Lo, int n4) {
    int i = blockIdx.x * blockDim.x + threadIdx.x;
    if (i >= n4) return;
    float4 v = __ldg((const float4*)X + i);
    uint32_t hi[2], lo[2];
    split4(v, hi, lo);
    ((uint2*)Hi)[i] = make_uint2(hi[0], hi[1]);
    ((uint2*)Lo)[i] = make_uint2(lo[0], lo[1]);
}

__global__ void split3_kernel(const float* __restrict__ Wa,
                              const float* __restrict__ Wb,
                              const float* __restrict__ Wc) {
    const int n4 = DD * DD / 4;
    int i = blockIdx.x * blockDim.x + threadIdx.x;
    if (i >= n4) return;
    const float* W = (blockIdx.y == 0) ? Wa : (blockIdx.y == 1) ? Wb : Wc;
    size_t off = (size_t)blockIdx.y * (DD * DD / 4);
    float4 v = __ldg((const float4*)W + i);
    uint32_t hi[2], lo[2];
    split4(v, hi, lo);
    ((uint2*)g_w123_hi)[off + i] = make_uint2(hi[0], hi[1]);
    ((uint2*)g_w123_lo)[off + i] = make_uint2(lo[0], lo[1]);
}

// ---------------- SpMM (emits split bf16 output) ----------------
__global__ void __launch_bounds__(256) spmm_split_kernel(const float* __restrict__ X,
                                                         __nv_bfloat16* __restrict__ Mhi,
                                                         __nv_bfloat16* __restrict__ Mlo) {
    int wg = (blockIdx.x * blockDim.x + threadIdx.x) >> 5;
    if (wg >= NN) return;
    int lane = threadIdx.x & 31;
    int s0 = g_rowptr[wg], s1 = g_rowptr[wg + 1];
    float4 a0 = {0, 0, 0, 0}, a1 = {0, 0, 0, 0};
    for (int e = s0; e < s1; e++) {
        int s = g_col[e];
        float ns = g_norm_s[s];
        const float4* xp = (const float4*)(X + (size_t)s * DD);
        float4 v0 = __ldg(xp + lane);
        float4 v1 = __ldg(xp + lane + 32);
        a0.x += v0.x * ns; a0.y += v0.y * ns; a0.z += v0.z * ns; a0.w += v0.w * ns;
        a1.x += v1.x * ns; a1.y += v1.y * ns; a1.z += v1.z * ns; a1.w += v1.w * ns;
    }
    float nd = g_norm_d[wg];
    a0.x *= nd; a0.y *= nd; a0.z *= nd; a0.w *= nd;
    a1.x *= nd; a1.y *= nd; a1.z *= nd; a1.w *= nd;
    uint32_t hi[2], lo[2];
    size_t base = (size_t)wg * DD;
    split4(a0, hi, lo);
    ((uint2*)(Mhi + base))[lane] = make_uint2(hi[0], hi[1]);
    ((uint2*)(Mlo + base))[lane] = make_uint2(lo[0], lo[1]);
    split4(a1, hi, lo);
    ((uint2*)(Mhi + base))[lane + 32] = make_uint2(hi[0], hi[1]);
    ((uint2*)(Mlo + base))[lane + 32] = make_uint2(lo[0], lo[1]);
}

// ---------------- BN apply ----------------
__global__ void bn_elu_kernel(float* __restrict__ X,
                              const float* __restrict__ gamma,
                              const float* __restrict__ beta) {
    int idx = blockIdx.x * blockDim.x + threadIdx.x;
    int col = idx & (DD - 1);
    float mu = g_colsum[col] * (1.f / NN);
    float var = g_colsq[col] * (1.f / NN) - mu * mu;
    float inv = rsqrtf(var + 1e-5f);
    float y = gamma[col] * (X[idx] - mu) * inv + beta[col];
    X[idx] = (y > 0.f) ? y : expm1f(y);
}

// ======================= persistent pre-split bf16x3 GEMM =======================
#define SA_STR 80
#define SB_STR 528
#define A_BUF (64 * SA_STR)
#define B_BUF (32 * SB_STR)
#define STAGE_SZ (2 * A_BUF + 2 * B_BUF)
#define GEMM_SMEM (2 * STAGE_SZ)
#define PERSIST 296

__global__ void __launch_bounds__(256, 2) gemm_ps_kernel(
    const __nv_bfloat16* __restrict__ Ahi, const __nv_bfloat16* __restrict__ Alo,
    const __nv_bfloat16* __restrict__ Bhi, const __nv_bfloat16* __restrict__ Blo,
    const float* __restrict__ bias, float* __restrict__ C,
    int M, int K, int nTiles, int doStats)
{
    extern __shared__ __align__(16) uint8_t smem[];
    const uint32_t sbase = smem_u32(smem);

    const int tid = threadIdx.x;
    const int wid = tid >> 5;
    const int lane = tid & 31;
    const int warpM = (wid & 1) * 32;
    const int warpN = (wid >> 1) * 64;

    const int a_row = tid >> 2;
    const int a_cb  = (tid & 3) * 16;
    const uint32_t a_dst = (uint32_t)(a_row * SA_STR + a_cb);
    const int b_row = tid >> 5;
    const int b_cb  = (tid & 31) * 16;

    const int m8 = lane >> 3;
    const int r8 = lane & 7;
    const uint32_t aoff = (uint32_t)(((m8 & 1) * 8 + r8) * SA_STR + (m8 >> 1) * 16);
    const uint32_t boff = (uint32_t)(((m8 & 1) * 8 + r8) * SB_STR + (m8 >> 1) * 16);

    const int KT = K >> 5;

    auto load_chunk = [&](int t, int k0, int stg) {
        const int bm = t * 64;
        uint32_t st = sbase + stg * STAGE_SZ;
        const uint32_t ok = (bm + a_row < M) ? 16u : 0u;
        const uint8_t* ah = (const uint8_t*)Ahi + ((size_t)(bm + a_row) * K + k0) * 2 + a_cb;
        const uint8_t* al = (const uint8_t*)Alo + ((size_t)(bm + a_row) * K + k0) * 2 + a_cb;
        cp16(st + a_dst, ah, ok);
        cp16(st + A_BUF + a_dst, al, ok);
        uint32_t db = st + 2 * A_BUF;
#pragma unroll
        for (int j = 0; j < 4; j++) {
            int r = b_row + 8 * j;
            cp16f(db + r * SB_STR + b_cb,
                  (const uint8_t*)Bhi + (size_t)(k0 + r) * 512 + b_cb);
            cp16f(db + B_BUF + r * SB_STR + b_cb,
                  (const uint8_t*)Blo + (size_t)(k0 + r) * 512 + b_cb);
        }
        cp_commit();
    };

    int buf = 0;
    int tile = blockIdx.x;
    if (tile >= nTiles) return;

    load_chunk(tile, 0, 0);

    for (; tile < nTiles; tile += gridDim.x) {
        const int bm = tile * 64;
        float acc[2][8][4];
#pragma unroll
        for (int i = 0; i < 2; i++)
#pragma unroll
            for (int j = 0; j < 8; j++)
#pragma unroll
                for (int q = 0; q < 4; q++) acc[i][j][q] = 0.f;

        for (int it = 0; it < KT; ++it) {
            if (it + 1 < KT) {
                load_chunk(tile, (it + 1) << 5, buf ^ 1);
                cp_wait<1>();
            } else {
                int nt2 = tile + gridDim.x;
                if (nt2 < nTiles) {
                    load_chunk(nt2, 0, buf ^ 1);
                    cp_wait<1>();
                } else {
                    cp_wait<0>();
                }
            }
            __syncthreads();

            const uint32_t st = sbase + buf * STAGE_SZ;
#pragma unroll
            for (int kh = 0; kh < 2; kh++) {
                uint32_t ah[2][4], al[2][4], b[16];
                const uint32_t aW = st + (uint32_t)(warpM * SA_STR + kh * 32) + aoff;
                const uint32_t bW = st + 2 * A_BUF + (uint32_t)(kh * 16 * SB_STR + warpN * 2) + boff;
#pragma unroll
                for (int mt = 0; mt < 2; mt++)
                    ldsm4(ah[mt], aW + mt * 16 * SA_STR);
#pragma unroll
                for (int p = 0; p < 4; p++) ldsm4t(&b[4 * p], bW + p * 32);
#pragma unroll
                for (int mt = 0; mt < 2; mt++)
#pragma unroll
                    for (int nt = 0; nt < 8; nt++)
                        mma_bf16(acc[mt][nt], ah[mt], &b[nt * 2]);
#pragma unroll
                for (int mt = 0; mt < 2; mt++)
                    ldsm4(al[mt], aW + A_BUF + mt * 16 * SA_STR);
#pragma unroll
                for (int mt = 0; mt < 2; mt++)
#pragma unroll
                    for (int nt = 0; nt < 8; nt++)
                        mma_bf16(acc[mt][nt], al[mt], &b[nt * 2]);
#pragma unroll
                for (int p = 0; p < 4; p++) ldsm4t(&b[4 * p], bW + B_BUF + p * 32);
#pragma unroll
                for (int mt = 0; mt < 2; mt++)
#pragma unroll
                    for (int nt = 0; nt < 8; nt++)
                        mma_bf16(acc[mt][nt], ah[mt], &b[nt * 2]);
            }
            __syncthreads();
            buf ^= 1;
        }

        // ---- epilogue: store + optional fused BN column stats ----
        const int g = lane >> 2;
        const int tg = lane & 3;
#pragma unroll
        for (int nt = 0; nt < 8; nt++) {
            const int col0 = warpN + nt * 8 + tg * 2;
            const float bi0 = __ldg(bias + col0);
            const float bi1 = __ldg(bias + col0 + 1);
            float s0 = 0.f, s1 = 0.f, q0 = 0.f, q1 = 0.f;
#pragma unroll
            for (int mt = 0; mt < 2; mt++) {
                int row0 = bm + warpM + mt * 16 + g;
                int row1 = row0 + 8;
                if (row0 < M) {
                    float v0 = acc[mt][nt][0] + bi0;
                    float v1 = acc[mt][nt][1] + bi1;
                    C[(size_t)row0 * 256 + col0]     = v0;
                    C[(size_t)row0 * 256 + col0 + 1] = v1;
                    s0 += v0; q0 += v0 * v0;
                    s1 += v1; q1 += v1 * v1;
                }
                if (row1 < M) {
                    float v2 = acc[mt][nt][2] + bi0;
                    float v3 = acc[mt][nt][3] + bi1;
                    C[(size_t)row1 * 256 + col0]     = v2;
                    C[(size_t)row1 * 256 + col0 + 1] = v3;
                    s0 += v2; q0 += v2 * v2;
                    s1 += v3; q1 += v3 * v3;
                }
            }
            if (doStats) {
#pragma unroll
                for (int off = 4; off < 32; off <<= 1) {
                    s0 += __shfl_xor_sync(0xffffffffu, s0, off);
                    s1 += __shfl_xor_sync(0xffffffffu, s1, off);
                    q0 += __shfl_xor_sync(0xffffffffu, q0, off);
                    q1 += __shfl_xor_sync(0xffffffffu, q1, off);
                }
                if (g == 0) {
                    atomicAdd(&g_colsum[col0], s0);
                    atomicAdd(&g_colsum[col0 + 1], s1);
                    atomicAdd(&g_colsq[col0], q0);
                    atomicAdd(&g_colsq[col0 + 1], q1);
                }
            }
        }
    }
}

// ======================= logits GEMM (in-kernel split, 128x128 tile) =======================
#define SA_STRIDE 80
#define SB_STRIDE 272
__global__ void __launch_bounds__(256) gemm_mma_kernel(
    const float* __restrict__ A, const float* __restrict__ B,
    const float* __restrict__ bias, float* __restrict__ C,
    int M, int N, int K)
{
    __shared__ __align__(16) uint8_t sAhi[128 * SA_STRIDE];
    __shared__ __align__(16) uint8_t sAlo[128 * SA_STRIDE];
    __shared__ __align__(16) uint8_t sBhi[32 * SB_STRIDE];
    __shared__ __align__(16) uint8_t sBlo[32 * SB_STRIDE];

    const int tid = threadIdx.x;
    const int wid = tid >> 5;
    const int lane = tid & 31;
    const int warpM = (wid & 3) * 32;
    const int warpN = (wid >> 2) * 64;
    const int bm = blockIdx.x * 128;
    const int bn = blockIdx.y * 128;

    const uint32_t uAhi = smem_u32(sAhi);
    const uint32_t uAlo = smem_u32(sAlo);
    const uint32_t uBhi = smem_u32(sBhi);
    const uint32_t uBlo = smem_u32(sBlo);

    const int m8 = lane >> 3;
    const int r8 = lane & 7;
    const uint32_t aoff = (uint32_t)(((m8 & 1) * 8 + r8) * SA_STRIDE + (m8 >> 1) * 16);
    const uint32_t boff = (uint32_t)(((m8 & 1) * 8 + r8) * SB_STRIDE + (m8 >> 1) * 16);

    float acc[2][8][4];
#pragma unroll
    for (int i = 0; i < 2; i++)
#pragma unroll
        for (int j = 0; j < 8; j++)
#pragma unroll
            for (int q = 0; q < 4; q++) acc[i][j][q] = 0.f;

    const int arow = tid >> 1;
    const int acb  = (tid & 1) * 16;
    const int bkr  = tid >> 3;
    const int bcb  = (tid & 7) * 16;

    for (int k0 = 0; k0 < K; k0 += 32) {
        {
            float4 f[4];
            if (bm + arow < M) {
                const float4* p = (const float4*)(A + (size_t)(bm + arow) * K + k0 + acb);
#pragma unroll
                for (int q = 0; q < 4; q++) f[q] = __ldg(p + q);
            } else {
#pragma unroll
                for (int q = 0; q < 4; q++) f[q] = make_float4(0.f, 0.f, 0.f, 0.f);
            }
            uint32_t hi[8], lo[8];
#pragma unroll
            for (int q = 0; q < 4; q++) split4(f[q], hi + 2 * q, lo + 2 * q);
            uint8_t* dh = sAhi + arow * SA_STRIDE + acb * 2;
            uint8_t* dl = sAlo + arow * SA_STRIDE + acb * 2;
            *(uint4*)dh        = make_uint4(hi[0], hi[1], hi[2], hi[3]);
            *(uint4*)(dh + 16) = make_uint4(hi[4], hi[5], hi[6], hi[7]);
            *(uint4*)dl        = make_uint4(lo[0], lo[1], lo[2], lo[3]);
            *(uint4*)(dl + 16) = make_uint4(lo[4], lo[5], lo[6], lo[7]);
        }
        {
            float4 f[4];
            const size_t brow = (size_t)(k0 + bkr) * N;
            if (bn + bcb + 15 < N) {
                const float4* p = (const float4*)(B + brow + bn + bcb);
#pragma unroll
                for (int q = 0; q < 4; q++) f[q] = __ldg(p + q);
            } else {
                float v[16];
#pragma unroll
                for (int i = 0; i < 16; i++) {
                    int c = bn + bcb + i;
                    v[i] = (c < N) ? __ldg(B + brow + c) : 0.f;
                }
#pragma unroll
                for (int q = 0; q < 4; q++) f[q] = make_float4(v[4*q], v[4*q+1], v[4*q+2], v[4*q+3]);
            }
            uint32_t hi[8], lo[8];
#pragma unroll
            for (int q = 0; q < 4; q++) split4(f[q], hi + 2 * q, lo + 2 * q);
            uint8_t* dh = sBhi + bkr * SB_STRIDE + bcb * 2;
            uint8_t* dl = sBlo + bkr * SB_STRIDE + bcb * 2;
            *(uint4*)dh        = make_uint4(hi[0], hi[1], hi[2], hi[3]);
            *(uint4*)(dh + 16) = make_uint4(hi[4], hi[5], hi[6], hi[7]);
            *(uint4*)dl        = make_uint4(lo[0], lo[1], lo[2], lo[3]);
            *(uint4*)(dl + 16) = make_uint4(lo[4], lo[5], lo[6], lo[7]);
        }
        __syncthreads();

#pragma unroll
        for (int kh = 0; kh < 2; kh++) {
            uint32_t afrag[2][4];
            uint32_t bh[16], bl[16];
            const uint32_t aW = (uint32_t)(warpM * SA_STRIDE + kh * 32) + aoff;
            const uint32_t bW = (uint32_t)(kh * 16 * SB_STRIDE + warpN * 2) + boff;
#pragma unroll
            for (int mt = 0; mt < 2; mt++)
                ldsm4(afrag[mt], uAhi + aW + mt * 16 * SA_STRIDE);
#pragma unroll
            for (int p = 0; p < 4; p++)
                ldsm4t(&bh[4 * p], uBhi + bW + p * 32);
#pragma unroll
            for (int mt = 0; mt < 2; mt++)
#pragma unroll
                for (int nt = 0; nt < 8; nt++)
                    mma_bf16(acc[mt][nt], afrag[mt], &bh[nt * 2]);
#pragma unroll
            for (int p = 0; p < 4; p++)
                ldsm4t(&bl[4 * p], uBlo + bW + p * 32);
#pragma unroll
            for (int mt = 0; mt < 2; mt++)
#pragma unroll
                for (int nt = 0; nt < 8; nt++)
                    mma_bf16(acc[mt][nt], afrag[mt], &bl[nt * 2]);
#pragma unroll
            for (int mt = 0; mt < 2; mt++)
                ldsm4(afrag[mt], uAlo + aW + mt * 16 * SA_STRIDE);
#pragma unroll
            for (int mt = 0; mt < 2; mt++)
#pragma unroll
                for (int nt = 0; nt < 8; nt++)
                    mma_bf16(acc[mt][nt], afrag[mt], &bh[nt * 2]);
        }
        __syncthreads();
    }

    const int g  = lane >> 2;
    const int tg = lane & 3;
#pragma unroll
    for (int mt = 0; mt < 2; mt++) {
        int row0 = bm + warpM + mt * 16 + g;
        int row1 = row0 + 8;
#pragma unroll
        for (int nt = 0; nt < 8; nt++) {
            int col0 = bn + warpN + nt * 8 + tg * 2;
            if (col0 < N) {
                float bi0 = __ldg(bias + col0);
                bool c1ok = (col0 + 1 < N);
                float bi1 = c1ok ? __ldg(bias + col0 + 1) : 0.f;
                if (row0 < M) {
                    C[(size_t)row0 * N + col0] = acc[mt][nt][0] + bi0;
                    if (c1ok) C[(size_t)row0 * N + col0 + 1] = acc[mt][nt][1] + bi1;
                }
                if (row1 < M) {
                    C[(size_t)row1 * N + col0] = acc[mt][nt][2] + bi0;
                    if (c1ok) C[(size_t)row1 * N + col0 + 1] = acc[mt][nt][3] + bi1;
                }
            }
        }
    }
}

// ======================= launch =======================
extern "C" void kernel_launch(void* const* d_in, const int* in_sizes, int n_in,
                              void* d_out, int out_size) {
    const float* feat  = (const float*)d_in[0];
    const int*   src   = (const int*)d_in[1];
    const int*   dst   = (const int*)d_in[2];
    const float* W_fc  = (const float*)d_in[3];
    const float* b_fc  = (const float*)d_in[4];
    const float* W1    = (const float*)d_in[5];
    const float* b1    = (const float*)d_in[6];
    const float* W2    = (const float*)d_in[7];
    const float* b2    = (const float*)d_in[8];
    const float* W3    = (const float*)d_in[9];
    const float* b3    = (const float*)d_in[10];
    const float* gamma = (const float*)d_in[11];
    const float* beta  = (const float*)d_in[12];
    const float* W_lin = (const float*)d_in[13];
    const float* b_lin = (const float*)d_in[14];

    float* out_x      = (float*)d_out;
    float* out_logits = (float*)d_out + (size_t)NN * DD;

    float* gx;  cudaGetSymbolAddress((void**)&gx, g_x);
    __nv_bfloat16 *fh, *fl, *mh, *ml, *wh, *wl, *w3h, *w3l;
    cudaGetSymbolAddress((void**)&fh, g_feat_hi);
    cudaGetSymbolAddress((void**)&fl, g_feat_lo);
    cudaGetSymbolAddress((void**)&mh, g_m_hi);
    cudaGetSymbolAddress((void**)&ml, g_m_lo);
    cudaGetSymbolAddress((void**)&wh, g_w_hi);
    cudaGetSymbolAddress((void**)&wl, g_w_lo);
    cudaGetSymbolAddress((void**)&w3h, g_w123_hi);
    cudaGetSymbolAddress((void**)&w3l, g_w123_lo);

    cudaFuncSetAttribute(gemm_ps_kernel, cudaFuncAttributeMaxDynamicSharedMemorySize, GEMM_SMEM);

    int nscan = (NN + SCAN_CHUNK - 1) / SCAN_CHUNK;
    const int NT = (NN + 63) / 64;       // 782 tiles
    const int GP = (NT < PERSIST) ? NT : PERSIST;
    const int MT128 = (NN + 127) / 128;
    int spmm_blocks = (NN * 32 + 255) / 256;
    int elem_blocks = (NN * DD) / 256;

    zero_init_kernel<<<(NN + 255) / 256, 256>>>();                               // 1
    split_kernel<<<(NN * FF / 4 + 255) / 256, 256>>>(feat, fh, fl, NN * FF / 4); // 2
    split_kernel<<<(FF * DD / 4 + 255) / 256, 256>>>(W_fc, wh, wl, FF * DD / 4); // 3
    gemm_ps_kernel<<<GP, 256, GEMM_SMEM>>>(fh, fl, wh, wl, b_fc, gx, NN, FF, NT, 0); // 4 <-- captured

    dim3 g_s3((DD * DD / 4 + 255) / 256, 3);
    split3_kernel<<<g_s3, 256>>>(W1, W2, W3);
    count_deg_kernel<<<(EE + 255) / 256, 256>>>(src, dst);
    norms_kernel<<<(NN + 255) / 256, 256>>>();
    scan_part_kernel<<<nscan, SCAN_CHUNK>>>();
    scan_block_kernel<<<1, 128>>>(nscan);
    scan_add_kernel<<<nscan, SCAN_CHUNK>>>();
    fill_csr_kernel<<<(EE + 255) / 256, 256>>>(src, dst);

    // layer 1 (BN stats fused into GEMM epilogue)
    spmm_split_kernel<<<spmm_blocks, 256>>>(gx, mh, ml);
    zero_bn_kernel<<<1, 256>>>();
    gemm_ps_kernel<<<GP, 256, GEMM_SMEM>>>(mh, ml, w3h, w3l, b1, gx, NN, DD, NT, 1);
    bn_elu_kernel<<<elem_blocks, 256>>>(gx, gamma, beta);

    // layer 2
    spmm_split_kernel<<<spmm_blocks, 256>>>(gx, mh, ml);
    zero_bn_kernel<<<1, 256>>>();
    gemm_ps_kernel<<<GP, 256, GEMM_SMEM>>>(mh, ml, w3h + DD * DD, w3l + DD * DD, b2, gx, NN, DD, NT, 1);
    bn_elu_kernel<<<elem_blocks, 256>>>(gx, gamma, beta);

    // layer 3 (no BN) -> out_x
    spmm_split_kernel<<<spmm_blocks, 256>>>(gx, mh, ml);
    gemm_ps_kernel<<<GP, 256, GEMM_SMEM>>>(mh, ml, w3h + 2 * DD * DD, w3l + 2 * DD * DD, b3, out_x, NN, DD, NT, 0);

    // logits = out_x @ W_lin + b_lin
    dim3 g_lin(MT128, 1);
    gemm_mma_kernel<<<g_lin, 256>>>(out_x, W_lin, b_lin, out_logits, NN, CC, DD);
}